// round 1
// baseline (speedup 1.0000x reference)
#include <cuda_runtime.h>

// Problem constants (fixed by the dataset)
#define Bq  8
#define Tq  4096
#define Dq  1024
#define Hq  16
#define DHq 64
#define MAXU 64        // u = 41 at these shapes

// ---------------- scratch (static device memory; no allocations) ----------------
__device__ float g_K [(size_t)Bq * Tq * Dq];     // K projection  [B*T, D]
__device__ float g_V [(size_t)Bq * Tq * Dq];     // V projection  [B*T, D]
__device__ float g_Qs[(size_t)Bq * MAXU * Dq];   // gathered Q    [B*u, D]
__device__ float g_Y [(size_t)Bq * MAXU * Dq];   // ctx rows      [B*u, D]
__device__ float g_om[(size_t)Bq * Dq];          // per-batch mean output row

// =================================================================================
// Tiled SGEMM:  C[m,n] = sum_k A[arow(m),k] * B[n,k]  (+ bias[n])
// 128x128 tile, BK=16, 256 threads, 8x8 per thread.
// Optional: gatherA (A row -> b*Trows + idx[m%u]), scatterC (same map on C rows).
// =================================================================================
__global__ __launch_bounds__(256) void sgemm_abt(
    const float* __restrict__ A, const float* __restrict__ Bm, float* __restrict__ C,
    const float* __restrict__ bias, int M, int N, int K,
    int lda, int ldb, int ldc,
    const int* __restrict__ idx, int u, int Trows,
    int gatherA, int scatterC)
{
    __shared__ __align__(16) float As[16][132];
    __shared__ __align__(16) float Bs[16][132];

    const int tid = threadIdx.x;
    const int tx = tid & 15, ty = tid >> 4;
    const int bm = blockIdx.y * 128;
    const int bn = blockIdx.x * 128;

    const int lrow = tid >> 2;          // 0..63
    const int lk4  = (tid & 3) << 2;    // 0,4,8,12

    long long aoff[2]; bool aval[2];
    long long boff[2]; bool bval[2];
    #pragma unroll
    for (int i = 0; i < 2; i++) {
        int r = bm + lrow + i * 64;
        aval[i] = (r < M);
        int gr = 0;
        if (aval[i]) {
            gr = r;
            if (gatherA) { int bb = r / u; int jj = r - bb * u; gr = bb * Trows + idx[jj]; }
        }
        aoff[i] = (long long)gr * lda;

        int rn = bn + lrow + i * 64;
        bval[i] = (rn < N);
        boff[i] = (long long)(bval[i] ? rn : 0) * ldb;
    }

    float acc[8][8];
    #pragma unroll
    for (int i = 0; i < 8; i++)
        #pragma unroll
        for (int j = 0; j < 8; j++) acc[i][j] = 0.f;

    for (int k0 = 0; k0 < K; k0 += 16) {
        #pragma unroll
        for (int i = 0; i < 2; i++) {
            float4 v = make_float4(0.f, 0.f, 0.f, 0.f);
            if (aval[i]) v = *(const float4*)(A + aoff[i] + k0 + lk4);
            int rr = lrow + i * 64;
            As[lk4 + 0][rr] = v.x; As[lk4 + 1][rr] = v.y;
            As[lk4 + 2][rr] = v.z; As[lk4 + 3][rr] = v.w;

            float4 w = make_float4(0.f, 0.f, 0.f, 0.f);
            if (bval[i]) w = *(const float4*)(Bm + boff[i] + k0 + lk4);
            Bs[lk4 + 0][rr] = w.x; Bs[lk4 + 1][rr] = w.y;
            Bs[lk4 + 2][rr] = w.z; Bs[lk4 + 3][rr] = w.w;
        }
        __syncthreads();

        #pragma unroll
        for (int kk = 0; kk < 16; kk++) {
            float a[8], b[8];
            *(float4*)&a[0] = *(const float4*)&As[kk][ty * 8];
            *(float4*)&a[4] = *(const float4*)&As[kk][ty * 8 + 4];
            *(float4*)&b[0] = *(const float4*)&Bs[kk][tx * 8];
            *(float4*)&b[4] = *(const float4*)&Bs[kk][tx * 8 + 4];
            #pragma unroll
            for (int i = 0; i < 8; i++)
                #pragma unroll
                for (int j = 0; j < 8; j++)
                    acc[i][j] = fmaf(a[i], b[j], acc[i][j]);
        }
        __syncthreads();
    }

    #pragma unroll
    for (int i = 0; i < 8; i++) {
        int m = bm + ty * 8 + i;
        if (m >= M) continue;
        long long crow = m;
        if (scatterC) { int bb = m / u; int jj = m - bb * u; crow = (long long)bb * Trows + idx[jj]; }
        float* cp = C + crow * ldc + bn + tx * 8;
        #pragma unroll
        for (int j = 0; j < 8; j++) {
            float v = acc[i][j];
            if (bias) v += bias[bn + tx * 8 + j];
            cp[j] = v;
        }
    }
}

// =================================================================================
// Flash-style sparse attention: one block per (b,h).
// Qs rows (u<=48, padded) vs K/V tiles of 128. fp32 throughout, online softmax.
// =================================================================================
#define UQ  48
#define TBq 128
#define ATTN_SMEM_FLOATS (64*UQ + 64*(TBq+4) + TBq*(DHq+4) + TBq*(UQ+1))
#define ATTN_SMEM_BYTES  (ATTN_SMEM_FLOATS * 4)

__global__ __launch_bounds__(256) void attn_kernel(
    const float* __restrict__ Q, const float* __restrict__ Kg,
    const float* __restrict__ Vg, float* __restrict__ Y, int u)
{
    extern __shared__ __align__(16) float sm[];
    float* Qt = sm;                          // [64][UQ]   Q^T (pre-scaled)
    float* Ks = Qt + 64 * UQ;                // [64][TB+4] K tile transposed
    float* Vs = Ks + 64 * (TBq + 4);         // [TB][DH+4] V tile
    float* Ps = Vs + TBq * (DHq + 4);        // [TB][UQ+1] P^T

    const int tid = threadIdx.x;
    const int tx = tid & 15, ty = tid >> 4;
    const int bh = blockIdx.x;
    const int b = bh / Hq, h = bh % Hq;
    const float scale = 0.125f;              // 1/sqrt(64)

    // Load Q (scaled), transposed; pad rows >= u with zeros.
    for (int i = tid; i < UQ * 64; i += 256) {
        int r = i >> 6, d = i & 63;
        float v = 0.f;
        if (r < u) v = Q[((size_t)(b * u + r)) * Dq + h * DHq + d] * scale;
        Qt[d * UQ + r] = v;
    }

    const int r0  = ty * 3;   // 16*3 = 48 rows
    const int tc0 = tx * 8;   // score cols
    const int c0  = tx * 4;   // ctx cols

    float m_run[3] = {-1e30f, -1e30f, -1e30f};
    float l_run[3] = {0.f, 0.f, 0.f};
    float acc[3][4] = {};

    for (int t0g = 0; t0g < Tq; t0g += TBq) {
        __syncthreads();  // previous iter done with Ks/Vs/Ps (also fences Qt first iter)

        // Load K (transposed) and V tiles
        for (int l = tid; l < TBq * 16; l += 256) {
            int t = l >> 4, d4 = (l & 15) << 2;
            size_t grow = (size_t)(b * Tq + t0g + t) * Dq + h * DHq + d4;
            float4 kv = *(const float4*)(Kg + grow);
            Ks[(d4 + 0) * (TBq + 4) + t] = kv.x;
            Ks[(d4 + 1) * (TBq + 4) + t] = kv.y;
            Ks[(d4 + 2) * (TBq + 4) + t] = kv.z;
            Ks[(d4 + 3) * (TBq + 4) + t] = kv.w;
            *(float4*)&Vs[t * (DHq + 4) + d4] = *(const float4*)(Vg + grow);
        }
        __syncthreads();

        // S[3][8] = Q tile @ K tile^T
        float s[3][8] = {};
        #pragma unroll 4
        for (int d = 0; d < 64; d++) {
            float a0 = Qt[d * UQ + r0 + 0];
            float a1 = Qt[d * UQ + r0 + 1];
            float a2 = Qt[d * UQ + r0 + 2];
            float4 b0 = *(const float4*)&Ks[d * (TBq + 4) + tc0];
            float4 b1 = *(const float4*)&Ks[d * (TBq + 4) + tc0 + 4];
            float bb[8] = {b0.x, b0.y, b0.z, b0.w, b1.x, b1.y, b1.z, b1.w};
            #pragma unroll
            for (int j = 0; j < 8; j++) {
                s[0][j] = fmaf(a0, bb[j], s[0][j]);
                s[1][j] = fmaf(a1, bb[j], s[1][j]);
                s[2][j] = fmaf(a2, bb[j], s[2][j]);
            }
        }

        // Online softmax update (rows of one ty live in a single warp-half)
        #pragma unroll
        for (int i = 0; i < 3; i++) {
            float tmax = s[i][0];
            #pragma unroll
            for (int j = 1; j < 8; j++) tmax = fmaxf(tmax, s[i][j]);
            tmax = fmaxf(tmax, __shfl_xor_sync(0xffffffffu, tmax, 1));
            tmax = fmaxf(tmax, __shfl_xor_sync(0xffffffffu, tmax, 2));
            tmax = fmaxf(tmax, __shfl_xor_sync(0xffffffffu, tmax, 4));
            tmax = fmaxf(tmax, __shfl_xor_sync(0xffffffffu, tmax, 8));

            float mnew = fmaxf(m_run[i], tmax);
            float corr = __expf(m_run[i] - mnew);
            float rsum = 0.f;
            #pragma unroll
            for (int j = 0; j < 8; j++) {
                float p = __expf(s[i][j] - mnew);
                s[i][j] = p;
                rsum += p;
            }
            rsum += __shfl_xor_sync(0xffffffffu, rsum, 1);
            rsum += __shfl_xor_sync(0xffffffffu, rsum, 2);
            rsum += __shfl_xor_sync(0xffffffffu, rsum, 4);
            rsum += __shfl_xor_sync(0xffffffffu, rsum, 8);

            l_run[i] = l_run[i] * corr + rsum;
            m_run[i] = mnew;
            #pragma unroll
            for (int j = 0; j < 4; j++) acc[i][j] *= corr;
        }

        // Store P^T
        #pragma unroll
        for (int i = 0; i < 3; i++)
            #pragma unroll
            for (int j = 0; j < 8; j++)
                Ps[(tc0 + j) * (UQ + 1) + r0 + i] = s[i][j];
        __syncthreads();

        // acc += P @ V
        #pragma unroll 4
        for (int t = 0; t < TBq; t++) {
            float p0 = Ps[t * (UQ + 1) + r0 + 0];
            float p1 = Ps[t * (UQ + 1) + r0 + 1];
            float p2 = Ps[t * (UQ + 1) + r0 + 2];
            float4 v = *(const float4*)&Vs[t * (DHq + 4) + c0];
            acc[0][0] = fmaf(p0, v.x, acc[0][0]); acc[0][1] = fmaf(p0, v.y, acc[0][1]);
            acc[0][2] = fmaf(p0, v.z, acc[0][2]); acc[0][3] = fmaf(p0, v.w, acc[0][3]);
            acc[1][0] = fmaf(p1, v.x, acc[1][0]); acc[1][1] = fmaf(p1, v.y, acc[1][1]);
            acc[1][2] = fmaf(p1, v.z, acc[1][2]); acc[1][3] = fmaf(p1, v.w, acc[1][3]);
            acc[2][0] = fmaf(p2, v.x, acc[2][0]); acc[2][1] = fmaf(p2, v.y, acc[2][1]);
            acc[2][2] = fmaf(p2, v.z, acc[2][2]); acc[2][3] = fmaf(p2, v.w, acc[2][3]);
        }
    }

    #pragma unroll
    for (int i = 0; i < 3; i++) {
        int r = r0 + i;
        if (r < u) {
            float inv = 1.f / l_run[i];
            #pragma unroll
            for (int j = 0; j < 4; j++)
                Y[((size_t)(b * u + r)) * Dq + h * DHq + c0 + j] = acc[i][j] * inv;
        }
    }
}

// =================================================================================
// Mean of ctx rows -> project through Wo^T + bo -> per-batch constant output row.
// grid (8 n-chunks, B), 128 threads: ym computed redundantly per block (cheap).
// =================================================================================
__global__ __launch_bounds__(128) void meanproj_kernel(
    const float* __restrict__ Y, const float* __restrict__ Wo,
    const float* __restrict__ bo, float* __restrict__ om, int u)
{
    __shared__ __align__(16) float ym[Dq];
    const int b = blockIdx.y;
    const int n0 = blockIdx.x * 128;

    for (int d = threadIdx.x; d < Dq; d += 128) {
        float sacc = 0.f;
        for (int j = 0; j < u; j++) sacc += Y[((size_t)(b * u + j)) * Dq + d];
        ym[d] = sacc * (1.f / (float)u);
    }
    __syncthreads();

    const int n = n0 + threadIdx.x;
    const float4* wrow = (const float4*)(Wo + (size_t)n * Dq);
    float accv = bo[n];
    #pragma unroll 4
    for (int d4 = 0; d4 < Dq / 4; d4++) {
        float4 w  = wrow[d4];
        float4 y4 = *(const float4*)&ym[d4 * 4];
        accv = fmaf(y4.x, w.x, accv);
        accv = fmaf(y4.y, w.y, accv);
        accv = fmaf(y4.z, w.z, accv);
        accv = fmaf(y4.w, w.w, accv);
    }
    om[b * Dq + n] = accv;
}

// =================================================================================
// Broadcast fill: out[b,t,:] = om[b,:] for all t (idx rows overwritten after).
// =================================================================================
__global__ __launch_bounds__(256) void fill_kernel(
    const float4* __restrict__ om4, float4* __restrict__ out4)
{
    const int total4 = Bq * Tq * (Dq / 4);
    for (int i = blockIdx.x * blockDim.x + threadIdx.x; i < total4;
         i += gridDim.x * blockDim.x) {
        int c4 = i & 255;          // Dq/4 = 256
        int bt = i >> 8;
        int b  = bt >> 12;         // Tq = 4096
        out4[i] = __ldg(&om4[(b << 8) + c4]);
    }
}

// =================================================================================
extern "C" void kernel_launch(void* const* d_in, const int* in_sizes, int n_in,
                              void* d_out, int out_size)
{
    const float* x  = (const float*)d_in[0];
    const float* Wq = (const float*)d_in[1];
    const float* Wk = (const float*)d_in[2];
    const float* Wv = (const float*)d_in[3];
    const float* Wo = (const float*)d_in[4];
    const float* bo = (const float*)d_in[5];
    const int*  idx = (const int*)  d_in[6];
    const int u = in_sizes[6];                 // 41 at these shapes
    float* out = (float*)d_out;

    float *pK, *pV, *pQs, *pY, *pom;
    cudaGetSymbolAddress((void**)&pK,  g_K);
    cudaGetSymbolAddress((void**)&pV,  g_V);
    cudaGetSymbolAddress((void**)&pQs, g_Qs);
    cudaGetSymbolAddress((void**)&pY,  g_Y);
    cudaGetSymbolAddress((void**)&pom, g_om);

    cudaFuncSetAttribute(attn_kernel, cudaFuncAttributeMaxDynamicSharedMemorySize,
                         ATTN_SMEM_BYTES);

    const dim3 blk(256);
    const int MBT = Bq * Tq;              // 32768
    const int Mu  = Bq * u;               // 328

    // 1) K = x @ Wk^T   2) V = x @ Wv^T   (the heavy work)
    sgemm_abt<<<dim3(Dq / 128, MBT / 128), blk>>>(
        x, Wk, pK, nullptr, MBT, Dq, Dq, Dq, Dq, Dq, nullptr, 1, Tq, 0, 0);
    sgemm_abt<<<dim3(Dq / 128, MBT / 128), blk>>>(
        x, Wv, pV, nullptr, MBT, Dq, Dq, Dq, Dq, Dq, nullptr, 1, Tq, 0, 0);

    // 3) Qs = x[idx rows] @ Wq^T  (gathered A rows)
    sgemm_abt<<<dim3(Dq / 128, (Mu + 127) / 128), blk>>>(
        x, Wq, pQs, nullptr, Mu, Dq, Dq, Dq, Dq, Dq, idx, u, Tq, 1, 0);

    // 4) flash attention over all T, only the u query rows
    attn_kernel<<<Bq * Hq, 256, ATTN_SMEM_BYTES>>>(pQs, pK, pV, pY, u);

    // 5) per-batch mean ctx row -> @ Wo^T + bo
    meanproj_kernel<<<dim3(Dq / 128, Bq), 128>>>(pY, Wo, bo, pom, u);

    // 6) broadcast the constant row to all T positions (128 MB store)
    fill_kernel<<<2048, 256>>>((const float4*)pom, (float4*)out);

    // 7) overwrite the u idx rows: out[b, idx[j], :] = Y_row @ Wo^T + bo
    sgemm_abt<<<dim3(Dq / 128, (Mu + 127) / 128), blk>>>(
        pY, Wo, out, bo, Mu, Dq, Dq, Dq, Dq, Dq, idx, u, Tq, 0, 1);
}

// round 3
// speedup vs baseline: 2.3952x; 2.3952x over previous
#include <cuda_runtime.h>
#include <cuda_bf16.h>
#include <cstdint>

// Problem constants (fixed by the dataset)
#define Bq  8
#define Tq  4096
#define Dq  1024
#define Hq  16
#define DHq 64
#define MAXU 64        // u = 41 at these shapes
#define RPAD 48        // per-head padded query rows (16*48 = 768 rows/batch)
#define RB   (Hq * RPAD)   // 768 rows per batch

// ---------------- scratch (static device memory; no allocations) ----------------
__device__ float g_S  [(size_t)Bq * RB * Tq];           // scores fp32          96 MB
__device__ __nv_bfloat16 g_Phi[(size_t)Bq * RB * Tq];   // attn hi              48 MB
__device__ __nv_bfloat16 g_Plo[(size_t)Bq * RB * Tq];   // attn lo              48 MB
__device__ __nv_bfloat16 g_xhi[(size_t)Bq * Tq * Dq];   // x split hi           64 MB
__device__ __nv_bfloat16 g_xlo[(size_t)Bq * Tq * Dq];   // x split lo           64 MB
__device__ __nv_bfloat16 g_QWhi[(size_t)Bq * RB * Dq];  // QW hi                12 MB
__device__ __nv_bfloat16 g_QWlo[(size_t)Bq * RB * Dq];  // QW lo                12 MB
__device__ float g_Z  [(size_t)Bq * RB * Dq];           // attn @ x             24 MB
__device__ float g_Qs [(size_t)Bq * MAXU * Dq];         // gathered Q proj
__device__ float g_Y  [(size_t)Bq * MAXU * Dq];         // ctx rows
__device__ float g_om [(size_t)Bq * Dq];                // per-batch output row

// ---------------- PTX helpers (sm_80-level, compile for plain sm_103) -----------
__device__ __forceinline__ uint32_t smem_u32(const void* p) {
    uint32_t a;
    asm("{ .reg .u64 t; cvta.to.shared.u64 t, %1; cvt.u32.u64 %0, t; }" : "=r"(a) : "l"(p));
    return a;
}
#define CP16(saddr, gptr) \
    asm volatile("cp.async.cg.shared.global [%0], [%1], 16;" :: "r"(saddr), "l"(gptr))
#define CP_COMMIT() asm volatile("cp.async.commit_group;")
#define CP_WAIT1()  asm volatile("cp.async.wait_group 1;")
#define CP_WAIT0()  asm volatile("cp.async.wait_group 0;")

#define LDSM4(r0,r1,r2,r3,addr) \
    asm volatile("ldmatrix.sync.aligned.m8n8.x4.shared.b16 {%0,%1,%2,%3}, [%4];" \
        : "=r"(r0),"=r"(r1),"=r"(r2),"=r"(r3) : "r"(addr))
#define LDSM4T(r0,r1,r2,r3,addr) \
    asm volatile("ldmatrix.sync.aligned.m8n8.x4.trans.shared.b16 {%0,%1,%2,%3}, [%4];" \
        : "=r"(r0),"=r"(r1),"=r"(r2),"=r"(r3) : "r"(addr))

#define MMA_BF16(ac, A, b0, b1) \
    asm volatile("mma.sync.aligned.m16n8k16.row.col.f32.bf16.bf16.f32 " \
        "{%0,%1,%2,%3}, {%4,%5,%6,%7}, {%8,%9}, {%0,%1,%2,%3};" \
        : "+f"(ac[0]),"+f"(ac[1]),"+f"(ac[2]),"+f"(ac[3]) \
        : "r"(A[0]),"r"(A[1]),"r"(A[2]),"r"(A[3]), "r"(b0),"r"(b1))

// =================================================================================
// fp32 -> bf16 hi/lo split
// =================================================================================
__global__ __launch_bounds__(256) void split_bf16(
    const float4* __restrict__ src, uint2* __restrict__ hi, uint2* __restrict__ lo, int n4)
{
    for (int i = blockIdx.x * 256 + threadIdx.x; i < n4; i += gridDim.x * 256) {
        float4 v = src[i];
        __nv_bfloat16 h0 = __float2bfloat16(v.x), h1 = __float2bfloat16(v.y);
        __nv_bfloat16 h2 = __float2bfloat16(v.z), h3 = __float2bfloat16(v.w);
        __nv_bfloat16 l0 = __float2bfloat16(v.x - __bfloat162float(h0));
        __nv_bfloat16 l1 = __float2bfloat16(v.y - __bfloat162float(h1));
        __nv_bfloat16 l2 = __float2bfloat16(v.z - __bfloat162float(h2));
        __nv_bfloat16 l3 = __float2bfloat16(v.w - __bfloat162float(h3));
        __nv_bfloat162 hA = {h0, h1}, hB = {h2, h3}, lA = {l0, l1}, lB = {l2, l3};
        uint2 H, L;
        H.x = *(uint32_t*)&hA; H.y = *(uint32_t*)&hB;
        L.x = *(uint32_t*)&lA; L.y = *(uint32_t*)&lB;
        hi[i] = H; lo[i] = L;
    }
}

// =================================================================================
// Tiled fp32 SGEMM for the small gathered/scattered GEMMs (from round 1, passing)
// =================================================================================
__global__ __launch_bounds__(256) void sgemm_abt(
    const float* __restrict__ A, const float* __restrict__ Bm, float* __restrict__ C,
    const float* __restrict__ bias, int M, int N, int K,
    int lda, int ldb, int ldc,
    const int* __restrict__ idx, int u, int Trows,
    int gatherA, int scatterC)
{
    __shared__ __align__(16) float As[16][132];
    __shared__ __align__(16) float Bs[16][132];

    const int tid = threadIdx.x;
    const int tx = tid & 15, ty = tid >> 4;
    const int bm = blockIdx.y * 128;
    const int bn = blockIdx.x * 128;

    const int lrow = tid >> 2;
    const int lk4  = (tid & 3) << 2;

    long long aoff[2]; bool aval[2];
    long long boff[2]; bool bval[2];
    #pragma unroll
    for (int i = 0; i < 2; i++) {
        int r = bm + lrow + i * 64;
        aval[i] = (r < M);
        int gr = 0;
        if (aval[i]) {
            gr = r;
            if (gatherA) { int bb = r / u; int jj = r - bb * u; gr = bb * Trows + idx[jj]; }
        }
        aoff[i] = (long long)gr * lda;
        int rn = bn + lrow + i * 64;
        bval[i] = (rn < N);
        boff[i] = (long long)(bval[i] ? rn : 0) * ldb;
    }

    float acc[8][8];
    #pragma unroll
    for (int i = 0; i < 8; i++)
        #pragma unroll
        for (int j = 0; j < 8; j++) acc[i][j] = 0.f;

    for (int k0 = 0; k0 < K; k0 += 16) {
        #pragma unroll
        for (int i = 0; i < 2; i++) {
            float4 v = make_float4(0.f, 0.f, 0.f, 0.f);
            if (aval[i]) v = *(const float4*)(A + aoff[i] + k0 + lk4);
            int rrw = lrow + i * 64;
            As[lk4 + 0][rrw] = v.x; As[lk4 + 1][rrw] = v.y;
            As[lk4 + 2][rrw] = v.z; As[lk4 + 3][rrw] = v.w;
            float4 w = make_float4(0.f, 0.f, 0.f, 0.f);
            if (bval[i]) w = *(const float4*)(Bm + boff[i] + k0 + lk4);
            Bs[lk4 + 0][rrw] = w.x; Bs[lk4 + 1][rrw] = w.y;
            Bs[lk4 + 2][rrw] = w.z; Bs[lk4 + 3][rrw] = w.w;
        }
        __syncthreads();

        #pragma unroll
        for (int kk = 0; kk < 16; kk++) {
            float a[8], b[8];
            *(float4*)&a[0] = *(const float4*)&As[kk][ty * 8];
            *(float4*)&a[4] = *(const float4*)&As[kk][ty * 8 + 4];
            *(float4*)&b[0] = *(const float4*)&Bs[kk][tx * 8];
            *(float4*)&b[4] = *(const float4*)&Bs[kk][tx * 8 + 4];
            #pragma unroll
            for (int i = 0; i < 8; i++)
                #pragma unroll
                for (int j = 0; j < 8; j++)
                    acc[i][j] = fmaf(a[i], b[j], acc[i][j]);
        }
        __syncthreads();
    }

    #pragma unroll
    for (int i = 0; i < 8; i++) {
        int m = bm + ty * 8 + i;
        if (m >= M) continue;
        long long crow = m;
        if (scatterC) { int bb = m / u; int jj = m - bb * u; crow = (long long)bb * Trows + idx[jj]; }
        float* cp = C + crow * ldc + bn + tx * 8;
        #pragma unroll
        for (int j = 0; j < 8; j++) {
            float v = acc[i][j];
            if (bias) v += bias[bn + tx * 8 + j];
            cp[j] = v;
        }
    }
}

// =================================================================================
// QW[b, h*48+uu, :] = 0.125 * Qs[b,uu, h*64:(h+1)*64] @ Wk[h*64:(h+1)*64, :]
// Output split into bf16 hi/lo. Rows uu in [u,48) are zero.
// grid (Dq/128, B*H), 256 threads.
// =================================================================================
__global__ __launch_bounds__(256) void qw_kernel(
    const float* __restrict__ Qs, const float* __restrict__ Wk,
    __nv_bfloat16* __restrict__ QWhi, __nv_bfloat16* __restrict__ QWlo, int u)
{
    __shared__ float As[RPAD * 64];
    const int tid = threadIdx.x;
    const int bh = blockIdx.y;
    const int b = bh >> 4, h = bh & 15;
    const int n0 = blockIdx.x * 128;

    for (int i = tid; i < RPAD * 64; i += 256) {
        int uu = i >> 6, d = i & 63;
        As[i] = (uu < u) ? Qs[((size_t)(b * u + uu)) * Dq + h * 64 + d] : 0.f;
    }
    __syncthreads();

    const int n = n0 + (tid & 127);
    const int half = tid >> 7;          // 0/1 -> uu range half*24..+24
    float acc[24];
    #pragma unroll
    for (int j = 0; j < 24; j++) acc[j] = 0.f;

    for (int d = 0; d < 64; d++) {
        float w = __ldg(&Wk[(size_t)(h * 64 + d) * Dq + n]);
        #pragma unroll
        for (int j = 0; j < 24; j++)
            acc[j] = fmaf(As[(half * 24 + j) * 64 + d], w, acc[j]);
    }

    #pragma unroll
    for (int j = 0; j < 24; j++) {
        int uu = half * 24 + j;
        float v = acc[j] * 0.125f;       // 1/sqrt(64)
        __nv_bfloat16 hi = __float2bfloat16(v);
        __nv_bfloat16 lo = __float2bfloat16(v - __bfloat162float(hi));
        size_t o = ((size_t)b * RB + h * RPAD + uu) * Dq + n;
        QWhi[o] = hi; QWlo[o] = lo;
    }
}

// =================================================================================
// GEMM-S (tensor cores): S[b] = QW[b] @ x[b]^T
//   A [768 x 1024] K-contig (hi/lo), B [4096 x 1024] K-contig (hi/lo), C fp32.
//   BM=128 BN=128 BK=32, 8 warps (2x4), 2-stage cp.async pipeline, 3-MMA split.
// grid (Tq/128=32, RB/128=6, B=8)
// =================================================================================
#define ASTR 40                        // smem row stride in bf16 elems (80B)
#define S_MATB (128 * ASTR * 2)        // 10240 B per matrix
#define S_STAGE (4 * S_MATB)           // Ahi Alo Bhi Blo
#define S_SMEM (2 * S_STAGE)           // 81920

__global__ __launch_bounds__(256) void gemm_s_tc(
    const __nv_bfloat16* __restrict__ QWhi, const __nv_bfloat16* __restrict__ QWlo,
    const __nv_bfloat16* __restrict__ xhi,  const __nv_bfloat16* __restrict__ xlo,
    float* __restrict__ S)
{
    extern __shared__ __align__(16) char smraw[];
    const uint32_t smb = smem_u32(smraw);

    const int tid = threadIdx.x;
    const int wid = tid >> 5, lane = tid & 31;
    const int wm = wid >> 2, wn = wid & 3;
    const int lr = lane & 7, quad = lane >> 3;

    const int b  = blockIdx.z;
    const int bm = blockIdx.y * 128;
    const int bn = blockIdx.x * 128;

    const __nv_bfloat16* Ah = QWhi + ((size_t)b * RB + bm) * Dq;
    const __nv_bfloat16* Al = QWlo + ((size_t)b * RB + bm) * Dq;
    const __nv_bfloat16* Bh = xhi  + ((size_t)b * Tq + bn) * Dq;
    const __nv_bfloat16* Bl = xlo  + ((size_t)b * Tq + bn) * Dq;

    // ldmatrix lane-address components
    const uint32_t a_row = lr + ((quad & 1) << 3);
    const uint32_t a_col = (quad >> 1) << 3;
    const uint32_t b_row = lr + ((quad >> 1) << 3);
    const uint32_t b_col = (quad & 1) << 3;

    float acc[4][4][4];
    #pragma unroll
    for (int i = 0; i < 4; i++)
        #pragma unroll
        for (int j = 0; j < 4; j++)
            #pragma unroll
            for (int k = 0; k < 4; k++) acc[i][j][k] = 0.f;

    const int ldrow = tid >> 2;                 // 0..63
    const int ldc16 = (tid & 3) * 8;            // bf16 elems

    #define S_LOAD(st) do { \
        const int k0 = (st) * 32; \
        const uint32_t base = smb + ((st) & 1) * S_STAGE; \
        _Pragma("unroll") \
        for (int i = 0; i < 2; i++) { \
            const int row = ldrow + i * 64; \
            const size_t g = (size_t)row * Dq + k0 + ldc16; \
            const uint32_t so = (row * ASTR + ldc16) * 2; \
            CP16(base + so,              Ah + g); \
            CP16(base + S_MATB + so,     Al + g); \
            CP16(base + 2 * S_MATB + so, Bh + g); \
            CP16(base + 3 * S_MATB + so, Bl + g); \
        } \
        CP_COMMIT(); \
    } while (0)

    S_LOAD(0);
    const int NST = Dq / 32;                    // 32 stages
    for (int s = 0; s < NST; s++) {
        if (s + 1 < NST) { S_LOAD(s + 1); CP_WAIT1(); }
        else             { CP_WAIT0(); }
        __syncthreads();

        const uint32_t buf = smb + (s & 1) * S_STAGE;
        #pragma unroll
        for (int kk = 0; kk < 2; kk++) {
            const int kb = kk * 16;
            uint32_t Afh[4][4], Afl[4][4], Bfh[4][2], Bfl[4][2];
            #pragma unroll
            for (int mi = 0; mi < 4; mi++) {
                uint32_t ad = buf + ((wm * 64 + mi * 16 + a_row) * ASTR + kb + a_col) * 2;
                LDSM4(Afh[mi][0], Afh[mi][1], Afh[mi][2], Afh[mi][3], ad);
                LDSM4(Afl[mi][0], Afl[mi][1], Afl[mi][2], Afl[mi][3], ad + S_MATB);
            }
            #pragma unroll
            for (int jj = 0; jj < 2; jj++) {
                uint32_t ad = buf + 2 * S_MATB +
                              ((wn * 32 + jj * 16 + b_row) * ASTR + kb + b_col) * 2;
                uint32_t t0, t1, t2, t3;
                LDSM4(t0, t1, t2, t3, ad);
                Bfh[jj * 2][0] = t0; Bfh[jj * 2][1] = t1;
                Bfh[jj * 2 + 1][0] = t2; Bfh[jj * 2 + 1][1] = t3;
                LDSM4(t0, t1, t2, t3, ad + S_MATB);
                Bfl[jj * 2][0] = t0; Bfl[jj * 2][1] = t1;
                Bfl[jj * 2 + 1][0] = t2; Bfl[jj * 2 + 1][1] = t3;
            }
            #pragma unroll
            for (int mi = 0; mi < 4; mi++)
                #pragma unroll
                for (int ni = 0; ni < 4; ni++) {
                    MMA_BF16(acc[mi][ni], Afh[mi], Bfh[ni][0], Bfh[ni][1]);
                    MMA_BF16(acc[mi][ni], Afh[mi], Bfl[ni][0], Bfl[ni][1]);
                    MMA_BF16(acc[mi][ni], Afl[mi], Bfh[ni][0], Bfh[ni][1]);
                }
        }
        __syncthreads();
    }
    #undef S_LOAD

    #pragma unroll
    for (int mi = 0; mi < 4; mi++)
        #pragma unroll
        for (int ni = 0; ni < 4; ni++) {
            const int row = bm + wm * 64 + mi * 16 + (lane >> 2);
            const int col = bn + wn * 32 + ni * 8 + (lane & 3) * 2;
            float* p = S + ((size_t)b * RB + row) * Tq + col;
            *(float2*)p = make_float2(acc[mi][ni][0], acc[mi][ni][1]);
            *(float2*)(p + (size_t)8 * Tq) = make_float2(acc[mi][ni][2], acc[mi][ni][3]);
        }
}

// =================================================================================
// Softmax over T per row; writes P split into bf16 hi/lo. One block per row.
// =================================================================================
__global__ __launch_bounds__(256) void softmax_kernel(
    const float* __restrict__ S,
    __nv_bfloat16* __restrict__ Phi, __nv_bfloat16* __restrict__ Plo)
{
    __shared__ float red[8], red2[8];
    const size_t row = blockIdx.x;
    const float* src = S + row * Tq;
    const int tid = threadIdx.x;
    const int wid = tid >> 5, lane = tid & 31;

    float v[16];
    #pragma unroll
    for (int i = 0; i < 16; i++) v[i] = src[tid + (i << 8)];

    float m = v[0];
    #pragma unroll
    for (int i = 1; i < 16; i++) m = fmaxf(m, v[i]);
    #pragma unroll
    for (int o = 16; o > 0; o >>= 1) m = fmaxf(m, __shfl_xor_sync(0xffffffffu, m, o));
    if (lane == 0) red[wid] = m;
    __syncthreads();
    float M = red[0];
    #pragma unroll
    for (int w = 1; w < 8; w++) M = fmaxf(M, red[w]);

    float sum = 0.f;
    #pragma unroll
    for (int i = 0; i < 16; i++) { v[i] = __expf(v[i] - M); sum += v[i]; }
    #pragma unroll
    for (int o = 16; o > 0; o >>= 1) sum += __shfl_xor_sync(0xffffffffu, sum, o);
    if (lane == 0) red2[wid] = sum;
    __syncthreads();
    float L = 0.f;
    #pragma unroll
    for (int w = 0; w < 8; w++) L += red2[w];
    const float inv = 1.f / L;

    #pragma unroll
    for (int i = 0; i < 16; i++) {
        float p = v[i] * inv;
        __nv_bfloat16 hi = __float2bfloat16(p);
        __nv_bfloat16 lo = __float2bfloat16(p - __bfloat162float(hi));
        Phi[row * Tq + tid + (i << 8)] = hi;
        Plo[row * Tq + tid + (i << 8)] = lo;
    }
}

// =================================================================================
// GEMM-Z (tensor cores): Z[b] = P[b] @ x[b]
//   A [768 x 4096] K-contig (hi/lo); B = x[b] [4096(K) x 1024(N)] row-major -> trans ldmatrix.
//   BM=64 BN=128 BK=32. grid (Dq/128=8, RB/64=12, B=8)
// =================================================================================
#define Z_AMATB (64 * ASTR * 2)        // 5120
#define Z_BSTR 136
#define Z_BMATB (32 * Z_BSTR * 2)      // 8704
#define Z_STAGE (2 * Z_AMATB + 2 * Z_BMATB)  // 27648
#define Z_SMEM (2 * Z_STAGE)                 // 55296

__global__ __launch_bounds__(256) void gemm_z_tc(
    const __nv_bfloat16* __restrict__ Phi, const __nv_bfloat16* __restrict__ Plo,
    const __nv_bfloat16* __restrict__ xhi, const __nv_bfloat16* __restrict__ xlo,
    float* __restrict__ Z)
{
    extern __shared__ __align__(16) char smraw[];
    const uint32_t smb = smem_u32(smraw);

    const int tid = threadIdx.x;
    const int wid = tid >> 5, lane = tid & 31;
    const int wm = wid >> 2, wn = wid & 3;
    const int lr = lane & 7, quad = lane >> 3;

    const int b  = blockIdx.z;
    const int bm = blockIdx.y * 64;
    const int bn = blockIdx.x * 128;

    const __nv_bfloat16* Ah = Phi + ((size_t)b * RB + bm) * Tq;
    const __nv_bfloat16* Al = Plo + ((size_t)b * RB + bm) * Tq;
    const __nv_bfloat16* Bh = xhi + (size_t)b * Tq * Dq;
    const __nv_bfloat16* Bl = xlo + (size_t)b * Tq * Dq;

    const uint32_t a_row = lr + ((quad & 1) << 3);
    const uint32_t a_col = (quad >> 1) << 3;
    const uint32_t bz_row = lr + ((quad & 1) << 3);   // k dir
    const uint32_t bz_col = (quad >> 1) << 3;         // n dir

    float acc[2][4][4];
    #pragma unroll
    for (int i = 0; i < 2; i++)
        #pragma unroll
        for (int j = 0; j < 4; j++)
            #pragma unroll
            for (int k = 0; k < 4; k++) acc[i][j][k] = 0.f;

    const int arow = tid >> 2;                 // 0..63
    const int ac16 = (tid & 3) * 8;

    #define Z_LOAD(st) do { \
        const int k0 = (st) * 32; \
        const uint32_t base = smb + ((st) & 1) * Z_STAGE; \
        { \
            const size_t g = (size_t)arow * Tq + k0 + ac16; \
            const uint32_t so = (arow * ASTR + ac16) * 2; \
            CP16(base + so,           Ah + g); \
            CP16(base + Z_AMATB + so, Al + g); \
        } \
        _Pragma("unroll") \
        for (int i = 0; i < 2; i++) { \
            const int idx = tid + i * 256; \
            const int brow = idx >> 4, bc = (idx & 15) * 8; \
            const size_t g = (size_t)(k0 + brow) * Dq + bn + bc; \
            const uint32_t so = (brow * Z_BSTR + bc) * 2; \
            CP16(base + 2 * Z_AMATB + so,           Bh + g); \
            CP16(base + 2 * Z_AMATB + Z_BMATB + so, Bl + g); \
        } \
        CP_COMMIT(); \
    } while (0)

    Z_LOAD(0);
    const int NST = Tq / 32;                   // 128 stages
    for (int s = 0; s < NST; s++) {
        if (s + 1 < NST) { Z_LOAD(s + 1); CP_WAIT1(); }
        else             { CP_WAIT0(); }
        __syncthreads();

        const uint32_t buf = smb + (s & 1) * Z_STAGE;
        #pragma unroll
        for (int kk = 0; kk < 2; kk++) {
            const int kb = kk * 16;
            uint32_t Afh[2][4], Afl[2][4], Bfh[4][2], Bfl[4][2];
            #pragma unroll
            for (int mi = 0; mi < 2; mi++) {
                uint32_t ad = buf + ((wm * 32 + mi * 16 + a_row) * ASTR + kb + a_col) * 2;
                LDSM4(Afh[mi][0], Afh[mi][1], Afh[mi][2], Afh[mi][3], ad);
                LDSM4(Afl[mi][0], Afl[mi][1], Afl[mi][2], Afl[mi][3], ad + Z_AMATB);
            }
            #pragma unroll
            for (int jj = 0; jj < 2; jj++) {
                uint32_t ad = buf + 2 * Z_AMATB +
                              ((kb + bz_row) * Z_BSTR + wn * 32 + jj * 16 + bz_col) * 2;
                uint32_t t0, t1, t2, t3;
                LDSM4T(t0, t1, t2, t3, ad);
                Bfh[jj * 2][0] = t0; Bfh[jj * 2][1] = t1;
                Bfh[jj * 2 + 1][0] = t2; Bfh[jj * 2 + 1][1] = t3;
                LDSM4T(t0, t1, t2, t3, ad + Z_BMATB);
                Bfl[jj * 2][0] = t0; Bfl[jj * 2][1] = t1;
                Bfl[jj * 2 + 1][0] = t2; Bfl[jj * 2 + 1][1] = t3;
            }
            #pragma unroll
            for (int mi = 0; mi < 2; mi++)
                #pragma unroll
                for (int ni = 0; ni < 4; ni++) {
                    MMA_BF16(acc[mi][ni], Afh[mi], Bfh[ni][0], Bfh[ni][1]);
                    MMA_BF16(acc[mi][ni], Afh[mi], Bfl[ni][0], Bfl[ni][1]);
                    MMA_BF16(acc[mi][ni], Afl[mi], Bfh[ni][0], Bfh[ni][1]);
                }
        }
        __syncthreads();
    }
    #undef Z_LOAD

    #pragma unroll
    for (int mi = 0; mi < 2; mi++)
        #pragma unroll
        for (int ni = 0; ni < 4; ni++) {
            const int row = bm + wm * 32 + mi * 16 + (lane >> 2);
            const int col = bn + wn * 32 + ni * 8 + (lane & 3) * 2;
            float* p = Z + ((size_t)b * RB + row) * Dq + col;
            *(float2*)p = make_float2(acc[mi][ni][0], acc[mi][ni][1]);
            *(float2*)(p + (size_t)8 * Dq) = make_float2(acc[mi][ni][2], acc[mi][ni][3]);
        }
}

// =================================================================================
// ctx[b,h,uu,dh] = sum_e Z[b, h*48+uu, e] * Wv[h*64+dh, e]  -> Y[b*u+uu][h*64+dh]
// one block per (b,h), 256 threads.
// =================================================================================
__global__ __launch_bounds__(256) void ctx_kernel(
    const float* __restrict__ Z, const float* __restrict__ Wv,
    float* __restrict__ Y, int u)
{
    __shared__ float Zs[44 * 132];
    const int tid = threadIdx.x;
    const int bh = blockIdx.x;
    const int b = bh >> 4, h = bh & 15;
    const int dh = tid & 63, tg = tid >> 6;   // tg 0..3

    float acc[11];
    #pragma unroll
    for (int j = 0; j < 11; j++) acc[j] = 0.f;

    for (int e0 = 0; e0 < Dq; e0 += 128) {
        __syncthreads();
        for (int i = tid; i < 44 * 128; i += 256) {
            int uu = i >> 7, e = i & 127;
            Zs[uu * 132 + e] = (uu < u)
                ? Z[((size_t)b * RB + h * RPAD + uu) * Dq + e0 + e] : 0.f;
        }
        __syncthreads();

        const float* wv = Wv + (size_t)(h * 64 + dh) * Dq + e0;
        for (int e = 0; e < 128; e++) {
            float w = __ldg(&wv[e]);
            #pragma unroll
            for (int j = 0; j < 11; j++)
                acc[j] = fmaf(Zs[(tg + 4 * j) * 132 + e], w, acc[j]);
        }
    }

    #pragma unroll
    for (int j = 0; j < 11; j++) {
        int uu = tg + 4 * j;
        if (uu < u)
            Y[((size_t)(b * u + uu)) * Dq + h * 64 + dh] = acc[j];
    }
}

// =================================================================================
// Mean ctx row -> project through Wo^T + bo -> per-batch constant output row.
// =================================================================================
__global__ __launch_bounds__(128) void meanproj_kernel(
    const float* __restrict__ Y, const float* __restrict__ Wo,
    const float* __restrict__ bo, float* __restrict__ om, int u)
{
    __shared__ __align__(16) float ym[Dq];
    const int b = blockIdx.y;
    const int n0 = blockIdx.x * 128;

    for (int d = threadIdx.x; d < Dq; d += 128) {
        float sacc = 0.f;
        for (int j = 0; j < u; j++) sacc += Y[((size_t)(b * u + j)) * Dq + d];
        ym[d] = sacc * (1.f / (float)u);
    }
    __syncthreads();

    const int n = n0 + threadIdx.x;
    const float4* wrow = (const float4*)(Wo + (size_t)n * Dq);
    float accv = bo[n];
    #pragma unroll 4
    for (int d4 = 0; d4 < Dq / 4; d4++) {
        float4 w  = wrow[d4];
        float4 y4 = *(const float4*)&ym[d4 * 4];
        accv = fmaf(y4.x, w.x, accv);
        accv = fmaf(y4.y, w.y, accv);
        accv = fmaf(y4.z, w.z, accv);
        accv = fmaf(y4.w, w.w, accv);
    }
    om[b * Dq + n] = accv;
}

// =================================================================================
// Broadcast fill: out[b,t,:] = om[b,:] (idx rows overwritten after).
// =================================================================================
__global__ __launch_bounds__(256) void fill_kernel(
    const float4* __restrict__ om4, float4* __restrict__ out4)
{
    const int total4 = Bq * Tq * (Dq / 4);
    for (int i = blockIdx.x * blockDim.x + threadIdx.x; i < total4;
         i += gridDim.x * blockDim.x) {
        int c4 = i & 255;
        int bt = i >> 8;
        int b  = bt >> 12;
        out4[i] = __ldg(&om4[(b << 8) + c4]);
    }
}

// =================================================================================
extern "C" void kernel_launch(void* const* d_in, const int* in_sizes, int n_in,
                              void* d_out, int out_size)
{
    const float* x  = (const float*)d_in[0];
    const float* Wq = (const float*)d_in[1];
    const float* Wk = (const float*)d_in[2];
    const float* Wv = (const float*)d_in[3];
    const float* Wo = (const float*)d_in[4];
    const float* bo = (const float*)d_in[5];
    const int*  idx = (const int*)  d_in[6];
    const int u = in_sizes[6];                 // 41
    float* out = (float*)d_out;

    float *pS, *pZ, *pQs, *pY, *pom;
    __nv_bfloat16 *pxhi, *pxlo, *pQWhi, *pQWlo, *pPhi, *pPlo;
    cudaGetSymbolAddress((void**)&pS,   g_S);
    cudaGetSymbolAddress((void**)&pZ,   g_Z);
    cudaGetSymbolAddress((void**)&pQs,  g_Qs);
    cudaGetSymbolAddress((void**)&pY,   g_Y);
    cudaGetSymbolAddress((void**)&pom,  g_om);
    cudaGetSymbolAddress((void**)&pxhi, g_xhi);
    cudaGetSymbolAddress((void**)&pxlo, g_xlo);
    cudaGetSymbolAddress((void**)&pQWhi, g_QWhi);
    cudaGetSymbolAddress((void**)&pQWlo, g_QWlo);
    cudaGetSymbolAddress((void**)&pPhi, g_Phi);
    cudaGetSymbolAddress((void**)&pPlo, g_Plo);

    cudaFuncSetAttribute(gemm_s_tc, cudaFuncAttributeMaxDynamicSharedMemorySize, S_SMEM);
    cudaFuncSetAttribute(gemm_z_tc, cudaFuncAttributeMaxDynamicSharedMemorySize, Z_SMEM);

    const int Mu = Bq * u;                 // 328

    // 0) x -> bf16 hi/lo
    split_bf16<<<2048, 256>>>((const float4*)x, (uint2*)pxhi, (uint2*)pxlo,
                              Bq * Tq * Dq / 4);

    // 1) Qs = x[idx rows] @ Wq^T  (fp32, tiny)
    sgemm_abt<<<dim3(Dq / 128, (Mu + 127) / 128), 256>>>(
        x, Wq, pQs, nullptr, Mu, Dq, Dq, Dq, Dq, Dq, idx, u, Tq, 1, 0);

    // 2) QW = 0.125 * (Qs per-head) @ Wk_head  -> bf16 hi/lo, padded to 48 rows/head
    qw_kernel<<<dim3(Dq / 128, Bq * Hq), 256>>>(pQs, Wk, pQWhi, pQWlo, u);

    // 3) S[b] = QW[b] @ x[b]^T  (tensor cores)
    gemm_s_tc<<<dim3(Tq / 128, RB / 128, Bq), 256, S_SMEM>>>(
        pQWhi, pQWlo, pxhi, pxlo, pS);

    // 4) softmax rows -> P hi/lo
    softmax_kernel<<<Bq * RB, 256>>>(pS, pPhi, pPlo);

    // 5) Z[b] = P[b] @ x[b]  (tensor cores)
    gemm_z_tc<<<dim3(Dq / 128, RB / 64, Bq), 256, Z_SMEM>>>(
        pPhi, pPlo, pxhi, pxlo, pZ);

    // 6) ctx = Z @ Wv_head^T -> Y
    ctx_kernel<<<Bq * Hq, 256>>>(pZ, Wv, pY, u);

    // 7) per-batch mean ctx row -> @ Wo^T + bo
    meanproj_kernel<<<dim3(Dq / 128, Bq), 128>>>(pY, Wo, bo, pom, u);

    // 8) broadcast the constant row to all T positions
    fill_kernel<<<2048, 256>>>((const float4*)pom, (float4*)out);

    // 9) overwrite the u idx rows: out[b, idx[j], :] = Y_row @ Wo^T + bo
    sgemm_abt<<<dim3(Dq / 128, (Mu + 127) / 128), 256>>>(
        pY, Wo, out, bo, Mu, Dq, Dq, Dq, Dq, Dq, idx, u, Tq, 0, 1);
}

// round 5
// speedup vs baseline: 2.4084x; 1.0055x over previous
#include <cuda_runtime.h>
#include <cuda_bf16.h>
#include <cstdint>

// Problem constants (fixed by the dataset)
#define Bq  8
#define Tq  4096
#define Dq  1024
#define Hq  16
#define DHq 64
#define MAXU 64        // u = 41 at these shapes
#define RPAD 48        // per-head padded query rows (16*48 = 768 rows/batch)
#define RB   (Hq * RPAD)   // 768 rows per batch
#define ZPART ((size_t)Bq * RB * Dq)

// ---------------- scratch (static device memory; no allocations) ----------------
__device__ float g_S  [(size_t)Bq * RB * Tq];           // scores fp32          96 MB
__device__ __nv_bfloat16 g_Phi[(size_t)Bq * RB * Tq];   // attn hi              48 MB
__device__ __nv_bfloat16 g_Plo[(size_t)Bq * RB * Tq];   // attn lo              48 MB
__device__ __nv_bfloat16 g_xhi[(size_t)Bq * Tq * Dq];   // x split hi           64 MB
__device__ __nv_bfloat16 g_xlo[(size_t)Bq * Tq * Dq];   // x split lo           64 MB
__device__ __nv_bfloat16 g_QWhi[(size_t)Bq * RB * Dq];  // QW hi                12 MB
__device__ __nv_bfloat16 g_QWlo[(size_t)Bq * RB * Dq];  // QW lo                12 MB
__device__ float g_Zp [2 * ZPART];                      // split-K partials     48 MB
__device__ float g_Qs [(size_t)Bq * MAXU * Dq];         // gathered Q proj
__device__ float g_Y  [(size_t)Bq * MAXU * Dq];         // ctx rows
__device__ float g_om [(size_t)Bq * Dq];                // per-batch output row

// ---------------- PTX helpers (sm_80-level, compile for plain sm_103) -----------
__device__ __forceinline__ uint32_t smem_u32(const void* p) {
    uint32_t a;
    asm("{ .reg .u64 t; cvta.to.shared.u64 t, %1; cvt.u32.u64 %0, t; }" : "=r"(a) : "l"(p));
    return a;
}
#define CP16(saddr, gptr) \
    asm volatile("cp.async.cg.shared.global [%0], [%1], 16;" :: "r"(saddr), "l"(gptr))
#define CP_COMMIT() asm volatile("cp.async.commit_group;")
#define CP_WAIT0()  asm volatile("cp.async.wait_group 0;")

#define LDSM4(r0,r1,r2,r3,addr) \
    asm volatile("ldmatrix.sync.aligned.m8n8.x4.shared.b16 {%0,%1,%2,%3}, [%4];" \
        : "=r"(r0),"=r"(r1),"=r"(r2),"=r"(r3) : "r"(addr))
#define LDSM4T(r0,r1,r2,r3,addr) \
    asm volatile("ldmatrix.sync.aligned.m8n8.x4.trans.shared.b16 {%0,%1,%2,%3}, [%4];" \
        : "=r"(r0),"=r"(r1),"=r"(r2),"=r"(r3) : "r"(addr))

#define MMA_BF16(ac, A, b0, b1) \
    asm volatile("mma.sync.aligned.m16n8k16.row.col.f32.bf16.bf16.f32 " \
        "{%0,%1,%2,%3}, {%4,%5,%6,%7}, {%8,%9}, {%0,%1,%2,%3};" \
        : "+f"(ac[0]),"+f"(ac[1]),"+f"(ac[2]),"+f"(ac[3]) \
        : "r"(A[0]),"r"(A[1]),"r"(A[2]),"r"(A[3]), "r"(b0),"r"(b1))

// =================================================================================
// fp32 -> bf16 hi/lo split
// =================================================================================
__global__ __launch_bounds__(256) void split_bf16(
    const float4* __restrict__ src, uint2* __restrict__ hi, uint2* __restrict__ lo, int n4)
{
    for (int i = blockIdx.x * 256 + threadIdx.x; i < n4; i += gridDim.x * 256) {
        float4 v = src[i];
        __nv_bfloat16 h0 = __float2bfloat16(v.x), h1 = __float2bfloat16(v.y);
        __nv_bfloat16 h2 = __float2bfloat16(v.z), h3 = __float2bfloat16(v.w);
        __nv_bfloat16 l0 = __float2bfloat16(v.x - __bfloat162float(h0));
        __nv_bfloat16 l1 = __float2bfloat16(v.y - __bfloat162float(h1));
        __nv_bfloat16 l2 = __float2bfloat16(v.z - __bfloat162float(h2));
        __nv_bfloat16 l3 = __float2bfloat16(v.w - __bfloat162float(h3));
        __nv_bfloat162 hA = {h0, h1}, hB = {h2, h3}, lA = {l0, l1}, lB = {l2, l3};
        uint2 H, L;
        H.x = *(uint32_t*)&hA; H.y = *(uint32_t*)&hB;
        L.x = *(uint32_t*)&lA; L.y = *(uint32_t*)&lB;
        hi[i] = H; lo[i] = L;
    }
}

// =================================================================================
// Tiled fp32 SGEMM for the small gathered/scattered GEMMs
// =================================================================================
__global__ __launch_bounds__(256) void sgemm_abt(
    const float* __restrict__ A, const float* __restrict__ Bm, float* __restrict__ C,
    const float* __restrict__ bias, int M, int N, int K,
    int lda, int ldb, int ldc,
    const int* __restrict__ idx, int u, int Trows,
    int gatherA, int scatterC)
{
    __shared__ __align__(16) float As[16][132];
    __shared__ __align__(16) float Bs[16][132];

    const int tid = threadIdx.x;
    const int tx = tid & 15, ty = tid >> 4;
    const int bm = blockIdx.y * 128;
    const int bn = blockIdx.x * 128;

    const int lrow = tid >> 2;
    const int lk4  = (tid & 3) << 2;

    long long aoff[2]; bool aval[2];
    long long boff[2]; bool bval[2];
    #pragma unroll
    for (int i = 0; i < 2; i++) {
        int r = bm + lrow + i * 64;
        aval[i] = (r < M);
        int gr = 0;
        if (aval[i]) {
            gr = r;
            if (gatherA) { int bb = r / u; int jj = r - bb * u; gr = bb * Trows + idx[jj]; }
        }
        aoff[i] = (long long)gr * lda;
        int rn = bn + lrow + i * 64;
        bval[i] = (rn < N);
        boff[i] = (long long)(bval[i] ? rn : 0) * ldb;
    }

    float acc[8][8];
    #pragma unroll
    for (int i = 0; i < 8; i++)
        #pragma unroll
        for (int j = 0; j < 8; j++) acc[i][j] = 0.f;

    for (int k0 = 0; k0 < K; k0 += 16) {
        #pragma unroll
        for (int i = 0; i < 2; i++) {
            float4 v = make_float4(0.f, 0.f, 0.f, 0.f);
            if (aval[i]) v = *(const float4*)(A + aoff[i] + k0 + lk4);
            int rrw = lrow + i * 64;
            As[lk4 + 0][rrw] = v.x; As[lk4 + 1][rrw] = v.y;
            As[lk4 + 2][rrw] = v.z; As[lk4 + 3][rrw] = v.w;
            float4 w = make_float4(0.f, 0.f, 0.f, 0.f);
            if (bval[i]) w = *(const float4*)(Bm + boff[i] + k0 + lk4);
            Bs[lk4 + 0][rrw] = w.x; Bs[lk4 + 1][rrw] = w.y;
            Bs[lk4 + 2][rrw] = w.z; Bs[lk4 + 3][rrw] = w.w;
        }
        __syncthreads();

        #pragma unroll
        for (int kk = 0; kk < 16; kk++) {
            float a[8], b[8];
            *(float4*)&a[0] = *(const float4*)&As[kk][ty * 8];
            *(float4*)&a[4] = *(const float4*)&As[kk][ty * 8 + 4];
            *(float4*)&b[0] = *(const float4*)&Bs[kk][tx * 8];
            *(float4*)&b[4] = *(const float4*)&Bs[kk][tx * 8 + 4];
            #pragma unroll
            for (int i = 0; i < 8; i++)
                #pragma unroll
                for (int j = 0; j < 8; j++)
                    acc[i][j] = fmaf(a[i], b[j], acc[i][j]);
        }
        __syncthreads();
    }

    #pragma unroll
    for (int i = 0; i < 8; i++) {
        int m = bm + ty * 8 + i;
        if (m >= M) continue;
        long long crow = m;
        if (scatterC) { int bb = m / u; int jj = m - bb * u; crow = (long long)bb * Trows + idx[jj]; }
        float* cp = C + crow * ldc + bn + tx * 8;
        #pragma unroll
        for (int j = 0; j < 8; j++) {
            float v = acc[i][j];
            if (bias) v += bias[bn + tx * 8 + j];
            cp[j] = v;
        }
    }
}

// =================================================================================
// QW[b, h*48+uu, :] = 0.125 * Qs[b,uu, head] @ Wk[head, :]  -> bf16 hi/lo
// =================================================================================
__global__ __launch_bounds__(256) void qw_kernel(
    const float* __restrict__ Qs, const float* __restrict__ Wk,
    __nv_bfloat16* __restrict__ QWhi, __nv_bfloat16* __restrict__ QWlo, int u)
{
    __shared__ float As[RPAD * 64];
    const int tid = threadIdx.x;
    const int bh = blockIdx.y;
    const int b = bh >> 4, h = bh & 15;
    const int n0 = blockIdx.x * 128;

    for (int i = tid; i < RPAD * 64; i += 256) {
        int uu = i >> 6, d = i & 63;
        As[i] = (uu < u) ? Qs[((size_t)(b * u + uu)) * Dq + h * 64 + d] : 0.f;
    }
    __syncthreads();

    const int n = n0 + (tid & 127);
    const int half = tid >> 7;
    float acc[24];
    #pragma unroll
    for (int j = 0; j < 24; j++) acc[j] = 0.f;

    for (int d = 0; d < 64; d++) {
        float w = __ldg(&Wk[(size_t)(h * 64 + d) * Dq + n]);
        #pragma unroll
        for (int j = 0; j < 24; j++)
            acc[j] = fmaf(As[(half * 24 + j) * 64 + d], w, acc[j]);
    }

    #pragma unroll
    for (int j = 0; j < 24; j++) {
        int uu = half * 24 + j;
        float v = acc[j] * 0.125f;
        __nv_bfloat16 hi = __float2bfloat16(v);
        __nv_bfloat16 lo = __float2bfloat16(v - __bfloat162float(hi));
        size_t o = ((size_t)b * RB + h * RPAD + uu) * Dq + n;
        QWhi[o] = hi; QWlo[o] = lo;
    }
}

// =================================================================================
// GEMM-S: S[b] = QW[b] @ x[b]^T   BM=128 BN=128 BK=32, single-sync pipeline.
// grid (Tq/128=32, RB/128=6, B=8)
// =================================================================================
#define ASTR 40                        // smem row stride in bf16 elems (80B)
#define S_MATB (128 * ASTR * 2)        // 10240 B per matrix
#define S_STAGE (4 * S_MATB)           // Ahi Alo Bhi Blo
#define S_SMEM (2 * S_STAGE)           // 81920

__global__ __launch_bounds__(256) void gemm_s_tc(
    const __nv_bfloat16* __restrict__ QWhi, const __nv_bfloat16* __restrict__ QWlo,
    const __nv_bfloat16* __restrict__ xhi,  const __nv_bfloat16* __restrict__ xlo,
    float* __restrict__ S)
{
    extern __shared__ __align__(16) char smraw[];
    const uint32_t smb = smem_u32(smraw);

    const int tid = threadIdx.x;
    const int wid = tid >> 5, lane = tid & 31;
    const int wm = wid >> 2, wn = wid & 3;
    const int lr = lane & 7, quad = lane >> 3;

    const int b  = blockIdx.z;
    const int bm = blockIdx.y * 128;
    const int bn = blockIdx.x * 128;

    const __nv_bfloat16* Ah = QWhi + ((size_t)b * RB + bm) * Dq;
    const __nv_bfloat16* Al = QWlo + ((size_t)b * RB + bm) * Dq;
    const __nv_bfloat16* Bh = xhi  + ((size_t)b * Tq + bn) * Dq;
    const __nv_bfloat16* Bl = xlo  + ((size_t)b * Tq + bn) * Dq;

    const uint32_t a_row = lr + ((quad & 1) << 3);
    const uint32_t a_col = (quad >> 1) << 3;
    const uint32_t b_row = lr + ((quad >> 1) << 3);
    const uint32_t b_col = (quad & 1) << 3;

    float acc[4][4][4];
    #pragma unroll
    for (int i = 0; i < 4; i++)
        #pragma unroll
        for (int j = 0; j < 4; j++)
            #pragma unroll
            for (int k = 0; k < 4; k++) acc[i][j][k] = 0.f;

    const int ldrow = tid >> 2;
    const int ldc16 = (tid & 3) * 8;

    #define S_LOAD(st) do { \
        const int k0 = (st) * 32; \
        const uint32_t base = smb + ((st) & 1) * S_STAGE; \
        _Pragma("unroll") \
        for (int i = 0; i < 2; i++) { \
            const int row = ldrow + i * 64; \
            const size_t g = (size_t)row * Dq + k0 + ldc16; \
            const uint32_t so = (row * ASTR + ldc16) * 2; \
            CP16(base + so,              Ah + g); \
            CP16(base + S_MATB + so,     Al + g); \
            CP16(base + 2 * S_MATB + so, Bh + g); \
            CP16(base + 3 * S_MATB + so, Bl + g); \
        } \
        CP_COMMIT(); \
    } while (0)

    S_LOAD(0);
    const int NST = Dq / 32;                    // 32 stages
    for (int s = 0; s < NST; s++) {
        CP_WAIT0();
        __syncthreads();
        if (s + 1 < NST) S_LOAD(s + 1);         // overlaps compute(s)

        const uint32_t buf = smb + (s & 1) * S_STAGE;
        #pragma unroll
        for (int kk = 0; kk < 2; kk++) {
            const int kb = kk * 16;
            uint32_t Afh[4][4], Afl[4][4], Bfh[4][2], Bfl[4][2];
            #pragma unroll
            for (int mi = 0; mi < 4; mi++) {
                uint32_t ad = buf + ((wm * 64 + mi * 16 + a_row) * ASTR + kb + a_col) * 2;
                LDSM4(Afh[mi][0], Afh[mi][1], Afh[mi][2], Afh[mi][3], ad);
                LDSM4(Afl[mi][0], Afl[mi][1], Afl[mi][2], Afl[mi][3], ad + S_MATB);
            }
            #pragma unroll
            for (int jj = 0; jj < 2; jj++) {
                uint32_t ad = buf + 2 * S_MATB +
                              ((wn * 32 + jj * 16 + b_row) * ASTR + kb + b_col) * 2;
                uint32_t t0, t1, t2, t3;
                LDSM4(t0, t1, t2, t3, ad);
                Bfh[jj * 2][0] = t0; Bfh[jj * 2][1] = t1;
                Bfh[jj * 2 + 1][0] = t2; Bfh[jj * 2 + 1][1] = t3;
                LDSM4(t0, t1, t2, t3, ad + S_MATB);
                Bfl[jj * 2][0] = t0; Bfl[jj * 2][1] = t1;
                Bfl[jj * 2 + 1][0] = t2; Bfl[jj * 2 + 1][1] = t3;
            }
            #pragma unroll
            for (int mi = 0; mi < 4; mi++)
                #pragma unroll
                for (int ni = 0; ni < 4; ni++) {
                    MMA_BF16(acc[mi][ni], Afh[mi], Bfh[ni][0], Bfh[ni][1]);
                    MMA_BF16(acc[mi][ni], Afh[mi], Bfl[ni][0], Bfl[ni][1]);
                    MMA_BF16(acc[mi][ni], Afl[mi], Bfh[ni][0], Bfh[ni][1]);
                }
        }
    }
    #undef S_LOAD

    #pragma unroll
    for (int mi = 0; mi < 4; mi++)
        #pragma unroll
        for (int ni = 0; ni < 4; ni++) {
            const int row = bm + wm * 64 + mi * 16 + (lane >> 2);
            const int col = bn + wn * 32 + ni * 8 + (lane & 3) * 2;
            float* p = S + ((size_t)b * RB + row) * Tq + col;
            *(float2*)p = make_float2(acc[mi][ni][0], acc[mi][ni][1]);
            *(float2*)(p + (size_t)8 * Tq) = make_float2(acc[mi][ni][2], acc[mi][ni][3]);
        }
}

// =================================================================================
// Softmax over T per row; writes P split into bf16 hi/lo. One block per row.
// =================================================================================
__global__ __launch_bounds__(256) void softmax_kernel(
    const float* __restrict__ S,
    __nv_bfloat16* __restrict__ Phi, __nv_bfloat16* __restrict__ Plo)
{
    __shared__ float red[8], red2[8];
    const size_t row = blockIdx.x;
    const float* src = S + row * Tq;
    const int tid = threadIdx.x;
    const int wid = tid >> 5, lane = tid & 31;

    float v[16];
    #pragma unroll
    for (int i = 0; i < 16; i++) v[i] = src[tid + (i << 8)];

    float m = v[0];
    #pragma unroll
    for (int i = 1; i < 16; i++) m = fmaxf(m, v[i]);
    #pragma unroll
    for (int o = 16; o > 0; o >>= 1) m = fmaxf(m, __shfl_xor_sync(0xffffffffu, m, o));
    if (lane == 0) red[wid] = m;
    __syncthreads();
    float M = red[0];
    #pragma unroll
    for (int w = 1; w < 8; w++) M = fmaxf(M, red[w]);

    float sum = 0.f;
    #pragma unroll
    for (int i = 0; i < 16; i++) { v[i] = __expf(v[i] - M); sum += v[i]; }
    #pragma unroll
    for (int o = 16; o > 0; o >>= 1) sum += __shfl_xor_sync(0xffffffffu, sum, o);
    if (lane == 0) red2[wid] = sum;
    __syncthreads();
    float L = 0.f;
    #pragma unroll
    for (int w = 0; w < 8; w++) L += red2[w];
    const float inv = 1.f / L;

    #pragma unroll
    for (int i = 0; i < 16; i++) {
        float p = v[i] * inv;
        __nv_bfloat16 hi = __float2bfloat16(p);
        __nv_bfloat16 lo = __float2bfloat16(p - __bfloat162float(hi));
        Phi[row * Tq + tid + (i << 8)] = hi;
        Plo[row * Tq + tid + (i << 8)] = lo;
    }
}

// =================================================================================
// GEMM-Z: Zp[ks][b] = P[b][:, ksplit] @ x[b][ksplit, :]
//   BM=128 BN=128 BK=32, split-K=2, single-sync pipeline.
// grid (Dq/128=8, RB/128=6, B*2=16)
// =================================================================================
#define Z_AMATB (128 * ASTR * 2)       // 10240
#define Z_BSTR 136
#define Z_BMATB (32 * Z_BSTR * 2)      // 8704
#define Z_STAGE (2 * Z_AMATB + 2 * Z_BMATB)  // 37888
#define Z_SMEM (2 * Z_STAGE)                 // 75776
#define KSPL (Tq / 2)                        // 2048

__global__ __launch_bounds__(256) void gemm_z_tc(
    const __nv_bfloat16* __restrict__ Phi, const __nv_bfloat16* __restrict__ Plo,
    const __nv_bfloat16* __restrict__ xhi, const __nv_bfloat16* __restrict__ xlo,
    float* __restrict__ Zp)
{
    extern __shared__ __align__(16) char smraw[];
    const uint32_t smb = smem_u32(smraw);

    const int tid = threadIdx.x;
    const int wid = tid >> 5, lane = tid & 31;
    const int wm = wid >> 2, wn = wid & 3;
    const int lr = lane & 7, quad = lane >> 3;

    const int b  = blockIdx.z >> 1;
    const int ks = blockIdx.z & 1;
    const int bm = blockIdx.y * 128;
    const int bn = blockIdx.x * 128;

    const __nv_bfloat16* Ah = Phi + ((size_t)b * RB + bm) * Tq + (size_t)ks * KSPL;
    const __nv_bfloat16* Al = Plo + ((size_t)b * RB + bm) * Tq + (size_t)ks * KSPL;
    const __nv_bfloat16* Bh = xhi + ((size_t)b * Tq + (size_t)ks * KSPL) * Dq;
    const __nv_bfloat16* Bl = xlo + ((size_t)b * Tq + (size_t)ks * KSPL) * Dq;

    const uint32_t a_row = lr + ((quad & 1) << 3);
    const uint32_t a_col = (quad >> 1) << 3;
    const uint32_t bz_row = lr + ((quad & 1) << 3);   // k dir
    const uint32_t bz_col = (quad >> 1) << 3;         // n dir

    float acc[4][4][4];
    #pragma unroll
    for (int i = 0; i < 4; i++)
        #pragma unroll
        for (int j = 0; j < 4; j++)
            #pragma unroll
            for (int k = 0; k < 4; k++) acc[i][j][k] = 0.f;

    const int arow = tid >> 2;                 // 0..63 (x2 for 128 A rows)
    const int ac16 = (tid & 3) * 8;

    #define Z_LOAD(st) do { \
        const int k0 = (st) * 32; \
        const uint32_t base = smb + ((st) & 1) * Z_STAGE; \
        _Pragma("unroll") \
        for (int i = 0; i < 2; i++) { \
            const int row = arow + i * 64; \
            const size_t g = (size_t)row * Tq + k0 + ac16; \
            const uint32_t so = (row * ASTR + ac16) * 2; \
            CP16(base + so,           Ah + g); \
            CP16(base + Z_AMATB + so, Al + g); \
        } \
        _Pragma("unroll") \
        for (int i = 0; i < 2; i++) { \
            const int idx = tid + i * 256; \
            const int brow = idx >> 4, bc = (idx & 15) * 8; \
            const size_t g = (size_t)(k0 + brow) * Dq + bn + bc; \
            const uint32_t so = (brow * Z_BSTR + bc) * 2; \
            CP16(base + 2 * Z_AMATB + so,           Bh + g); \
            CP16(base + 2 * Z_AMATB + Z_BMATB + so, Bl + g); \
        } \
        CP_COMMIT(); \
    } while (0)

    Z_LOAD(0);
    const int NST = KSPL / 32;                 // 64 stages
    for (int s = 0; s < NST; s++) {
        CP_WAIT0();
        __syncthreads();
        if (s + 1 < NST) Z_LOAD(s + 1);

        const uint32_t buf = smb + (s & 1) * Z_STAGE;
        #pragma unroll
        for (int kk = 0; kk < 2; kk++) {
            const int kb = kk * 16;
            uint32_t Afh[4][4], Afl[4][4], Bfh[4][2], Bfl[4][2];
            #pragma unroll
            for (int mi = 0; mi < 4; mi++) {
                uint32_t ad = buf + ((wm * 64 + mi * 16 + a_row) * ASTR + kb + a_col) * 2;
                LDSM4(Afh[mi][0], Afh[mi][1], Afh[mi][2], Afh[mi][3], ad);
                LDSM4(Afl[mi][0], Afl[mi][1], Afl[mi][2], Afl[mi][3], ad + Z_AMATB);
            }
            #pragma unroll
            for (int jj = 0; jj < 2; jj++) {
                uint32_t ad = buf + 2 * Z_AMATB +
                              ((kb + bz_row) * Z_BSTR + wn * 32 + jj * 16 + bz_col) * 2;
                uint32_t t0, t1, t2, t3;
                LDSM4T(t0, t1, t2, t3, ad);
                Bfh[jj * 2][0] = t0; Bfh[jj * 2][1] = t1;
                Bfh[jj * 2 + 1][0] = t2; Bfh[jj * 2 + 1][1] = t3;
                LDSM4T(t0, t1, t2, t3, ad + Z_BMATB);
                Bfl[jj * 2][0] = t0; Bfl[jj * 2][1] = t1;
                Bfl[jj * 2 + 1][0] = t2; Bfl[jj * 2 + 1][1] = t3;
            }
            #pragma unroll
            for (int mi = 0; mi < 4; mi++)
                #pragma unroll
                for (int ni = 0; ni < 4; ni++) {
                    MMA_BF16(acc[mi][ni], Afh[mi], Bfh[ni][0], Bfh[ni][1]);
                    MMA_BF16(acc[mi][ni], Afh[mi], Bfl[ni][0], Bfl[ni][1]);
                    MMA_BF16(acc[mi][ni], Afl[mi], Bfh[ni][0], Bfh[ni][1]);
                }
        }
    }
    #undef Z_LOAD

    float* Zo = Zp + (size_t)ks * ZPART;
    #pragma unroll
    for (int mi = 0; mi < 4; mi++)
        #pragma unroll
        for (int ni = 0; ni < 4; ni++) {
            const int row = bm + wm * 64 + mi * 16 + (lane >> 2);
            const int col = bn + wn * 32 + ni * 8 + (lane & 3) * 2;
            float* p = Zo + ((size_t)b * RB + row) * Dq + col;
            *(float2*)p = make_float2(acc[mi][ni][0], acc[mi][ni][1]);
            *(float2*)(p + (size_t)8 * Dq) = make_float2(acc[mi][ni][2], acc[mi][ni][3]);
        }
}

// =================================================================================
// ctx[b,h,uu,dh] = sum_e (Zp0+Zp1)[b, h*48+uu, e] * Wv[h*64+dh, e] -> Y
// =================================================================================
__global__ __launch_bounds__(256) void ctx_kernel(
    const float* __restrict__ Zp, const float* __restrict__ Wv,
    float* __restrict__ Y, int u)
{
    __shared__ float Zs[44 * 132];
    const int tid = threadIdx.x;
    const int bh = blockIdx.x;
    const int b = bh >> 4, h = bh & 15;
    const int dh = tid & 63, tg = tid >> 6;

    float acc[11];
    #pragma unroll
    for (int j = 0; j < 11; j++) acc[j] = 0.f;

    for (int e0 = 0; e0 < Dq; e0 += 128) {
        __syncthreads();
        for (int i = tid; i < 44 * 128; i += 256) {
            int uu = i >> 7, e = i & 127;
            float z = 0.f;
            if (uu < u) {
                size_t o = ((size_t)b * RB + h * RPAD + uu) * Dq + e0 + e;
                z = Zp[o] + Zp[o + ZPART];
            }
            Zs[uu * 132 + e] = z;
        }
        __syncthreads();

        const float* wv = Wv + (size_t)(h * 64 + dh) * Dq + e0;
        for (int e = 0; e < 128; e++) {
            float w = __ldg(&wv[e]);
            #pragma unroll
            for (int j = 0; j < 11; j++)
                acc[j] = fmaf(Zs[(tg + 4 * j) * 132 + e], w, acc[j]);
        }
    }

    #pragma unroll
    for (int j = 0; j < 11; j++) {
        int uu = tg + 4 * j;
        if (uu < u)
            Y[((size_t)(b * u + uu)) * Dq + h * 64 + dh] = acc[j];
    }
}

// =================================================================================
// Mean ctx row -> project through Wo^T + bo -> per-batch constant output row.
// =================================================================================
__global__ __launch_bounds__(128) void meanproj_kernel(
    const float* __restrict__ Y, const float* __restrict__ Wo,
    const float* __restrict__ bo, float* __restrict__ om, int u)
{
    __shared__ __align__(16) float ym[Dq];
    const int b = blockIdx.y;
    const int n0 = blockIdx.x * 128;

    for (int d = threadIdx.x; d < Dq; d += 128) {
        float sacc = 0.f;
        for (int j = 0; j < u; j++) sacc += Y[((size_t)(b * u + j)) * Dq + d];
        ym[d] = sacc * (1.f / (float)u);
    }
    __syncthreads();

    const int n = n0 + threadIdx.x;
    const float4* wrow = (const float4*)(Wo + (size_t)n * Dq);
    float accv = bo[n];
    #pragma unroll 4
    for (int d4 = 0; d4 < Dq / 4; d4++) {
        float4 w  = wrow[d4];
        float4 y4 = *(const float4*)&ym[d4 * 4];
        accv = fmaf(y4.x, w.x, accv);
        accv = fmaf(y4.y, w.y, accv);
        accv = fmaf(y4.z, w.z, accv);
        accv = fmaf(y4.w, w.w, accv);
    }
    om[b * Dq + n] = accv;
}

// =================================================================================
// Broadcast fill: out[b,t,:] = om[b,:] (idx rows overwritten after).
// =================================================================================
__global__ __launch_bounds__(256) void fill_kernel(
    const float4* __restrict__ om4, float4* __restrict__ out4)
{
    const int total4 = Bq * Tq * (Dq / 4);
    for (int i = blockIdx.x * blockDim.x + threadIdx.x; i < total4;
         i += gridDim.x * blockDim.x) {
        int c4 = i & 255;
        int bt = i >> 8;
        int b  = bt >> 12;
        out4[i] = __ldg(&om4[(b << 8) + c4]);
    }
}

// =================================================================================
extern "C" void kernel_launch(void* const* d_in, const int* in_sizes, int n_in,
                              void* d_out, int out_size)
{
    const float* x  = (const float*)d_in[0];
    const float* Wq = (const float*)d_in[1];
    const float* Wk = (const float*)d_in[2];
    const float* Wv = (const float*)d_in[3];
    const float* Wo = (const float*)d_in[4];
    const float* bo = (const float*)d_in[5];
    const int*  idx = (const int*)  d_in[6];
    const int u = in_sizes[6];                 // 41
    float* out = (float*)d_out;

    float *pS, *pZp, *pQs, *pY, *pom;
    __nv_bfloat16 *pxhi, *pxlo, *pQWhi, *pQWlo, *pPhi, *pPlo;
    cudaGetSymbolAddress((void**)&pS,   g_S);
    cudaGetSymbolAddress((void**)&pZp,  g_Zp);
    cudaGetSymbolAddress((void**)&pQs,  g_Qs);
    cudaGetSymbolAddress((void**)&pY,   g_Y);
    cudaGetSymbolAddress((void**)&pom,  g_om);
    cudaGetSymbolAddress((void**)&pxhi, g_xhi);
    cudaGetSymbolAddress((void**)&pxlo, g_xlo);
    cudaGetSymbolAddress((void**)&pQWhi, g_QWhi);
    cudaGetSymbolAddress((void**)&pQWlo, g_QWlo);
    cudaGetSymbolAddress((void**)&pPhi, g_Phi);
    cudaGetSymbolAddress((void**)&pPlo, g_Plo);

    cudaFuncSetAttribute(gemm_s_tc, cudaFuncAttributeMaxDynamicSharedMemorySize, S_SMEM);
    cudaFuncSetAttribute(gemm_z_tc, cudaFuncAttributeMaxDynamicSharedMemorySize, Z_SMEM);

    const int Mu = Bq * u;                 // 328

    // 0) x -> bf16 hi/lo
    split_bf16<<<2048, 256>>>((const float4*)x, (uint2*)pxhi, (uint2*)pxlo,
                              Bq * Tq * Dq / 4);

    // 1) Qs = x[idx rows] @ Wq^T  (fp32, tiny)
    sgemm_abt<<<dim3(Dq / 128, (Mu + 127) / 128), 256>>>(
        x, Wq, pQs, nullptr, Mu, Dq, Dq, Dq, Dq, Dq, idx, u, Tq, 1, 0);

    // 2) QW = 0.125 * (Qs per-head) @ Wk_head  -> bf16 hi/lo
    qw_kernel<<<dim3(Dq / 128, Bq * Hq), 256>>>(pQs, Wk, pQWhi, pQWlo, u);

    // 3) S[b] = QW[b] @ x[b]^T  (tensor cores)
    gemm_s_tc<<<dim3(Tq / 128, RB / 128, Bq), 256, S_SMEM>>>(
        pQWhi, pQWlo, pxhi, pxlo, pS);

    // 4) softmax rows -> P hi/lo
    softmax_kernel<<<Bq * RB, 256>>>(pS, pPhi, pPlo);

    // 5) Zp[ks][b] = P[b] @ x[b]  (tensor cores, split-K=2)
    gemm_z_tc<<<dim3(Dq / 128, RB / 128, Bq * 2), 256, Z_SMEM>>>(
        pPhi, pPlo, pxhi, pxlo, pZp);

    // 6) ctx = (Zp0+Zp1) @ Wv_head^T -> Y
    ctx_kernel<<<Bq * Hq, 256>>>(pZp, Wv, pY, u);

    // 7) per-batch mean ctx row -> @ Wo^T + bo
    meanproj_kernel<<<dim3(Dq / 128, Bq), 128>>>(pY, Wo, bo, pom, u);

    // 8) broadcast the constant row to all T positions
    fill_kernel<<<2048, 256>>>((const float4*)pom, (float4*)out);

    // 9) overwrite the u idx rows: out[b, idx[j], :] = Y_row @ Wo^T + bo
    sgemm_abt<<<dim3(Dq / 128, (Mu + 127) / 128), 256>>>(
        pY, Wo, out, bo, Mu, Dq, Dq, Dq, Dq, Dq, idx, u, Tq, 0, 1);
}

// round 6
// speedup vs baseline: 2.8712x; 1.1922x over previous
#include <cuda_runtime.h>
#include <cuda_fp16.h>
#include <cstdint>

// Problem constants (fixed by the dataset)
#define Bq  8
#define Tq  4096
#define Dq  1024
#define Hq  16
#define DHq 64
#define MAXU 64        // u = 41 at these shapes
#define RPAD 48        // per-head padded query rows (16*48 = 768 rows/batch)
#define RB   (Hq * RPAD)   // 768 rows per batch
#define ZPART ((size_t)Bq * RB * Dq)

// ---------------- scratch (static device memory; no allocations) ----------------
__device__ float  g_S  [(size_t)Bq * RB * Tq];        // scores fp32          96 MB
__device__ __half g_Ph [(size_t)Bq * RB * Tq];        // attn fp16            48 MB
__device__ __half g_xhi[(size_t)Bq * Tq * Dq];        // x split hi (fp16)    64 MB
__device__ __half g_xlo[(size_t)Bq * Tq * Dq];        // x split lo (fp16)    64 MB
__device__ __half g_QWh[(size_t)Bq * RB * Dq];        // QW fp16              12 MB
__device__ float  g_Zp [2 * ZPART];                   // split-K partials     48 MB
__device__ float  g_Qs [(size_t)Bq * MAXU * Dq];      // gathered Q proj
__device__ float  g_Y  [(size_t)Bq * MAXU * Dq];      // ctx rows
__device__ float  g_om [(size_t)Bq * Dq];             // per-batch output row

// ---------------- PTX helpers (sm_80-level, compile for plain sm_103) -----------
__device__ __forceinline__ uint32_t smem_u32(const void* p) {
    uint32_t a;
    asm("{ .reg .u64 t; cvta.to.shared.u64 t, %1; cvt.u32.u64 %0, t; }" : "=r"(a) : "l"(p));
    return a;
}
#define CP16(saddr, gptr) \
    asm volatile("cp.async.cg.shared.global [%0], [%1], 16;" :: "r"(saddr), "l"(gptr))
#define CP_COMMIT() asm volatile("cp.async.commit_group;")
#define CP_WAIT1()  asm volatile("cp.async.wait_group 1;")
#define CP_WAIT0()  asm volatile("cp.async.wait_group 0;")

#define LDSM4(r0,r1,r2,r3,addr) \
    asm volatile("ldmatrix.sync.aligned.m8n8.x4.shared.b16 {%0,%1,%2,%3}, [%4];" \
        : "=r"(r0),"=r"(r1),"=r"(r2),"=r"(r3) : "r"(addr))
#define LDSM4T(r0,r1,r2,r3,addr) \
    asm volatile("ldmatrix.sync.aligned.m8n8.x4.trans.shared.b16 {%0,%1,%2,%3}, [%4];" \
        : "=r"(r0),"=r"(r1),"=r"(r2),"=r"(r3) : "r"(addr))

#define MMA_F16(ac, A, b0, b1) \
    asm volatile("mma.sync.aligned.m16n8k16.row.col.f32.f16.f16.f32 " \
        "{%0,%1,%2,%3}, {%4,%5,%6,%7}, {%8,%9}, {%0,%1,%2,%3};" \
        : "+f"(ac[0]),"+f"(ac[1]),"+f"(ac[2]),"+f"(ac[3]) \
        : "r"(A[0]),"r"(A[1]),"r"(A[2]),"r"(A[3]), "r"(b0),"r"(b1))

// =================================================================================
// fp32 -> fp16 hi/lo split (for x)
// =================================================================================
__global__ __launch_bounds__(256) void split_f16(
    const float4* __restrict__ src, uint2* __restrict__ hi, uint2* __restrict__ lo, int n4)
{
    for (int i = blockIdx.x * 256 + threadIdx.x; i < n4; i += gridDim.x * 256) {
        float4 v = src[i];
        __half h0 = __float2half(v.x), h1 = __float2half(v.y);
        __half h2 = __float2half(v.z), h3 = __float2half(v.w);
        __half l0 = __float2half(v.x - __half2float(h0));
        __half l1 = __float2half(v.y - __half2float(h1));
        __half l2 = __float2half(v.z - __half2float(h2));
        __half l3 = __float2half(v.w - __half2float(h3));
        __half2 hA = {h0, h1}, hB = {h2, h3}, lA = {l0, l1}, lB = {l2, l3};
        uint2 H, L;
        H.x = *(uint32_t*)&hA; H.y = *(uint32_t*)&hB;
        L.x = *(uint32_t*)&lA; L.y = *(uint32_t*)&lB;
        hi[i] = H; lo[i] = L;
    }
}

// =================================================================================
// Tiled fp32 SGEMM for the small gathered/scattered GEMMs
// =================================================================================
__global__ __launch_bounds__(256) void sgemm_abt(
    const float* __restrict__ A, const float* __restrict__ Bm, float* __restrict__ C,
    const float* __restrict__ bias, int M, int N, int K,
    int lda, int ldb, int ldc,
    const int* __restrict__ idx, int u, int Trows,
    int gatherA, int scatterC)
{
    __shared__ __align__(16) float As[16][132];
    __shared__ __align__(16) float Bs[16][132];

    const int tid = threadIdx.x;
    const int tx = tid & 15, ty = tid >> 4;
    const int bm = blockIdx.y * 128;
    const int bn = blockIdx.x * 128;

    const int lrow = tid >> 2;
    const int lk4  = (tid & 3) << 2;

    long long aoff[2]; bool aval[2];
    long long boff[2]; bool bval[2];
    #pragma unroll
    for (int i = 0; i < 2; i++) {
        int r = bm + lrow + i * 64;
        aval[i] = (r < M);
        int gr = 0;
        if (aval[i]) {
            gr = r;
            if (gatherA) { int bb = r / u; int jj = r - bb * u; gr = bb * Trows + idx[jj]; }
        }
        aoff[i] = (long long)gr * lda;
        int rn = bn + lrow + i * 64;
        bval[i] = (rn < N);
        boff[i] = (long long)(bval[i] ? rn : 0) * ldb;
    }

    float acc[8][8];
    #pragma unroll
    for (int i = 0; i < 8; i++)
        #pragma unroll
        for (int j = 0; j < 8; j++) acc[i][j] = 0.f;

    for (int k0 = 0; k0 < K; k0 += 16) {
        #pragma unroll
        for (int i = 0; i < 2; i++) {
            float4 v = make_float4(0.f, 0.f, 0.f, 0.f);
            if (aval[i]) v = *(const float4*)(A + aoff[i] + k0 + lk4);
            int rrw = lrow + i * 64;
            As[lk4 + 0][rrw] = v.x; As[lk4 + 1][rrw] = v.y;
            As[lk4 + 2][rrw] = v.z; As[lk4 + 3][rrw] = v.w;
            float4 w = make_float4(0.f, 0.f, 0.f, 0.f);
            if (bval[i]) w = *(const float4*)(Bm + boff[i] + k0 + lk4);
            Bs[lk4 + 0][rrw] = w.x; Bs[lk4 + 1][rrw] = w.y;
            Bs[lk4 + 2][rrw] = w.z; Bs[lk4 + 3][rrw] = w.w;
        }
        __syncthreads();

        #pragma unroll
        for (int kk = 0; kk < 16; kk++) {
            float a[8], b[8];
            *(float4*)&a[0] = *(const float4*)&As[kk][ty * 8];
            *(float4*)&a[4] = *(const float4*)&As[kk][ty * 8 + 4];
            *(float4*)&b[0] = *(const float4*)&Bs[kk][tx * 8];
            *(float4*)&b[4] = *(const float4*)&Bs[kk][tx * 8 + 4];
            #pragma unroll
            for (int i = 0; i < 8; i++)
                #pragma unroll
                for (int j = 0; j < 8; j++)
                    acc[i][j] = fmaf(a[i], b[j], acc[i][j]);
        }
        __syncthreads();
    }

    #pragma unroll
    for (int i = 0; i < 8; i++) {
        int m = bm + ty * 8 + i;
        if (m >= M) continue;
        long long crow = m;
        if (scatterC) { int bb = m / u; int jj = m - bb * u; crow = (long long)bb * Trows + idx[jj]; }
        float* cp = C + crow * ldc + bn + tx * 8;
        #pragma unroll
        for (int j = 0; j < 8; j++) {
            float v = acc[i][j];
            if (bias) v += bias[bn + tx * 8 + j];
            cp[j] = v;
        }
    }
}

// =================================================================================
// QW[b, h*48+uu, :] = 0.125 * Qs[b,uu, head] @ Wk[head, :]  -> fp16
// =================================================================================
__global__ __launch_bounds__(256) void qw_kernel(
    const float* __restrict__ Qs, const float* __restrict__ Wk,
    __half* __restrict__ QWh, int u)
{
    __shared__ float As[RPAD * 64];
    const int tid = threadIdx.x;
    const int bh = blockIdx.y;
    const int b = bh >> 4, h = bh & 15;
    const int n0 = blockIdx.x * 128;

    for (int i = tid; i < RPAD * 64; i += 256) {
        int uu = i >> 6, d = i & 63;
        As[i] = (uu < u) ? Qs[((size_t)(b * u + uu)) * Dq + h * 64 + d] : 0.f;
    }
    __syncthreads();

    const int n = n0 + (tid & 127);
    const int half_ = tid >> 7;
    float acc[24];
    #pragma unroll
    for (int j = 0; j < 24; j++) acc[j] = 0.f;

    for (int d = 0; d < 64; d++) {
        float w = __ldg(&Wk[(size_t)(h * 64 + d) * Dq + n]);
        #pragma unroll
        for (int j = 0; j < 24; j++)
            acc[j] = fmaf(As[(half_ * 24 + j) * 64 + d], w, acc[j]);
    }

    #pragma unroll
    for (int j = 0; j < 24; j++) {
        int uu = half_ * 24 + j;
        size_t o = ((size_t)b * RB + h * RPAD + uu) * Dq + n;
        QWh[o] = __float2half(acc[j] * 0.125f);
    }
}

// =================================================================================
// GEMM-S: S[b] = QW[b] @ x[b]^T   BM=128 BN=128 BK=32, 3-stage pipeline, 2 MMAs.
//   A = QW fp16 (single), B = x fp16 hi + lo.
// grid (Tq/128=32, RB/128=6, B=8)
// =================================================================================
#define ASTR 40                        // smem row stride in fp16 elems (80B)
#define S_MATB (128 * ASTR * 2)        // 10240 B per matrix
#define S_STAGE (3 * S_MATB)           // A, Bhi, Blo = 30720
#define S_SMEM (3 * S_STAGE)           // 92160

__global__ __launch_bounds__(256) void gemm_s_tc(
    const __half* __restrict__ QWh,
    const __half* __restrict__ xhi, const __half* __restrict__ xlo,
    float* __restrict__ S)
{
    extern __shared__ __align__(16) char smraw[];
    const uint32_t smb = smem_u32(smraw);

    const int tid = threadIdx.x;
    const int wid = tid >> 5, lane = tid & 31;
    const int wm = wid >> 2, wn = wid & 3;
    const int lr = lane & 7, quad = lane >> 3;

    const int b  = blockIdx.z;
    const int bm = blockIdx.y * 128;
    const int bn = blockIdx.x * 128;

    const __half* Ah = QWh + ((size_t)b * RB + bm) * Dq;
    const __half* Bh = xhi + ((size_t)b * Tq + bn) * Dq;
    const __half* Bl = xlo + ((size_t)b * Tq + bn) * Dq;

    const uint32_t a_row = lr + ((quad & 1) << 3);
    const uint32_t a_col = (quad >> 1) << 3;
    const uint32_t b_row = lr + ((quad >> 1) << 3);
    const uint32_t b_col = (quad & 1) << 3;

    float acc[4][4][4];
    #pragma unroll
    for (int i = 0; i < 4; i++)
        #pragma unroll
        for (int j = 0; j < 4; j++)
            #pragma unroll
            for (int k = 0; k < 4; k++) acc[i][j][k] = 0.f;

    const int ldrow = tid >> 2;
    const int ldc16 = (tid & 3) * 8;

    #define S_LOAD(st) do { \
        const int k0 = (st) * 32; \
        const uint32_t base = smb + ((st) % 3) * S_STAGE; \
        _Pragma("unroll") \
        for (int i = 0; i < 2; i++) { \
            const int row = ldrow + i * 64; \
            const size_t g = (size_t)row * Dq + k0 + ldc16; \
            const uint32_t so = (row * ASTR + ldc16) * 2; \
            CP16(base + so,              Ah + g); \
            CP16(base + S_MATB + so,     Bh + g); \
            CP16(base + 2 * S_MATB + so, Bl + g); \
        } \
        CP_COMMIT(); \
    } while (0)

    const int NST = Dq / 32;                    // 32 stages
    S_LOAD(0);
    S_LOAD(1);
    for (int s = 0; s < NST; s++) {
        if (s + 2 < NST) {
            CP_WAIT1();
            __syncthreads();
            S_LOAD(s + 2);
        } else {
            CP_WAIT0();
            __syncthreads();
        }

        const uint32_t buf = smb + (s % 3) * S_STAGE;
        #pragma unroll
        for (int kk = 0; kk < 2; kk++) {
            const int kb = kk * 16;
            uint32_t Af[4][4], Bfh[4][2], Bfl[4][2];
            #pragma unroll
            for (int mi = 0; mi < 4; mi++) {
                uint32_t ad = buf + ((wm * 64 + mi * 16 + a_row) * ASTR + kb + a_col) * 2;
                LDSM4(Af[mi][0], Af[mi][1], Af[mi][2], Af[mi][3], ad);
            }
            #pragma unroll
            for (int jj = 0; jj < 2; jj++) {
                uint32_t ad = buf + S_MATB +
                              ((wn * 32 + jj * 16 + b_row) * ASTR + kb + b_col) * 2;
                uint32_t t0, t1, t2, t3;
                LDSM4(t0, t1, t2, t3, ad);
                Bfh[jj * 2][0] = t0; Bfh[jj * 2][1] = t1;
                Bfh[jj * 2 + 1][0] = t2; Bfh[jj * 2 + 1][1] = t3;
                LDSM4(t0, t1, t2, t3, ad + S_MATB);
                Bfl[jj * 2][0] = t0; Bfl[jj * 2][1] = t1;
                Bfl[jj * 2 + 1][0] = t2; Bfl[jj * 2 + 1][1] = t3;
            }
            #pragma unroll
            for (int mi = 0; mi < 4; mi++)
                #pragma unroll
                for (int ni = 0; ni < 4; ni++) {
                    MMA_F16(acc[mi][ni], Af[mi], Bfh[ni][0], Bfh[ni][1]);
                    MMA_F16(acc[mi][ni], Af[mi], Bfl[ni][0], Bfl[ni][1]);
                }
        }
        __syncthreads();
    }
    #undef S_LOAD

    #pragma unroll
    for (int mi = 0; mi < 4; mi++)
        #pragma unroll
        for (int ni = 0; ni < 4; ni++) {
            const int row = bm + wm * 64 + mi * 16 + (lane >> 2);
            const int col = bn + wn * 32 + ni * 8 + (lane & 3) * 2;
            float* p = S + ((size_t)b * RB + row) * Tq + col;
            *(float2*)p = make_float2(acc[mi][ni][0], acc[mi][ni][1]);
            *(float2*)(p + (size_t)8 * Tq) = make_float2(acc[mi][ni][2], acc[mi][ni][3]);
        }
}

// =================================================================================
// Softmax over T per row; writes P as fp16. One block per row.
// =================================================================================
__global__ __launch_bounds__(256) void softmax_kernel(
    const float* __restrict__ S, __half* __restrict__ Ph)
{
    __shared__ float red[8], red2[8];
    const size_t row = blockIdx.x;
    const float* src = S + row * Tq;
    const int tid = threadIdx.x;
    const int wid = tid >> 5, lane = tid & 31;

    float v[16];
    #pragma unroll
    for (int i = 0; i < 16; i++) v[i] = src[tid + (i << 8)];

    float m = v[0];
    #pragma unroll
    for (int i = 1; i < 16; i++) m = fmaxf(m, v[i]);
    #pragma unroll
    for (int o = 16; o > 0; o >>= 1) m = fmaxf(m, __shfl_xor_sync(0xffffffffu, m, o));
    if (lane == 0) red[wid] = m;
    __syncthreads();
    float M = red[0];
    #pragma unroll
    for (int w = 1; w < 8; w++) M = fmaxf(M, red[w]);

    float sum = 0.f;
    #pragma unroll
    for (int i = 0; i < 16; i++) { v[i] = __expf(v[i] - M); sum += v[i]; }
    #pragma unroll
    for (int o = 16; o > 0; o >>= 1) sum += __shfl_xor_sync(0xffffffffu, sum, o);
    if (lane == 0) red2[wid] = sum;
    __syncthreads();
    float L = 0.f;
    #pragma unroll
    for (int w = 0; w < 8; w++) L += red2[w];
    const float inv = 1.f / L;

    #pragma unroll
    for (int i = 0; i < 16; i++)
        Ph[row * Tq + tid + (i << 8)] = __float2half(v[i] * inv);
}

// =================================================================================
// GEMM-Z: Zp[ks][b] = P[b][:, ksplit] @ x[b][ksplit, :]
//   BM=128 BN=128 BK=32, split-K=2, 3-stage pipeline, 2 MMAs.
// grid (Dq/128=8, RB/128=6, B*2=16)
// =================================================================================
#define Z_AMATB (128 * ASTR * 2)       // 10240
#define Z_BSTR 136
#define Z_BMATB (32 * Z_BSTR * 2)      // 8704
#define Z_STAGE (Z_AMATB + 2 * Z_BMATB)      // 27648
#define Z_SMEM (3 * Z_STAGE)                 // 82944
#define KSPL (Tq / 2)                        // 2048

__global__ __launch_bounds__(256) void gemm_z_tc(
    const __half* __restrict__ Ph,
    const __half* __restrict__ xhi, const __half* __restrict__ xlo,
    float* __restrict__ Zp)
{
    extern __shared__ __align__(16) char smraw[];
    const uint32_t smb = smem_u32(smraw);

    const int tid = threadIdx.x;
    const int wid = tid >> 5, lane = tid & 31;
    const int wm = wid >> 2, wn = wid & 3;
    const int lr = lane & 7, quad = lane >> 3;

    const int b  = blockIdx.z >> 1;
    const int ks = blockIdx.z & 1;
    const int bm = blockIdx.y * 128;
    const int bn = blockIdx.x * 128;

    const __half* Ah = Ph  + ((size_t)b * RB + bm) * Tq + (size_t)ks * KSPL;
    const __half* Bh = xhi + ((size_t)b * Tq + (size_t)ks * KSPL) * Dq;
    const __half* Bl = xlo + ((size_t)b * Tq + (size_t)ks * KSPL) * Dq;

    const uint32_t a_row = lr + ((quad & 1) << 3);
    const uint32_t a_col = (quad >> 1) << 3;
    const uint32_t bz_row = lr + ((quad & 1) << 3);   // k dir
    const uint32_t bz_col = (quad >> 1) << 3;         // n dir

    float acc[4][4][4];
    #pragma unroll
    for (int i = 0; i < 4; i++)
        #pragma unroll
        for (int j = 0; j < 4; j++)
            #pragma unroll
            for (int k = 0; k < 4; k++) acc[i][j][k] = 0.f;

    const int arow = tid >> 2;                 // 0..63
    const int ac16 = (tid & 3) * 8;

    #define Z_LOAD(st) do { \
        const int k0 = (st) * 32; \
        const uint32_t base = smb + ((st) % 3) * Z_STAGE; \
        _Pragma("unroll") \
        for (int i = 0; i < 2; i++) { \
            const int row = arow + i * 64; \
            const size_t g = (size_t)row * Tq + k0 + ac16; \
            const uint32_t so = (row * ASTR + ac16) * 2; \
            CP16(base + so, Ah + g); \
        } \
        _Pragma("unroll") \
        for (int i = 0; i < 2; i++) { \
            const int idx = tid + i * 256; \
            const int brow = idx >> 4, bc = (idx & 15) * 8; \
            const size_t g = (size_t)(k0 + brow) * Dq + bn + bc; \
            const uint32_t so = (brow * Z_BSTR + bc) * 2; \
            CP16(base + Z_AMATB + so,           Bh + g); \
            CP16(base + Z_AMATB + Z_BMATB + so, Bl + g); \
        } \
        CP_COMMIT(); \
    } while (0)

    const int NST = KSPL / 32;                 // 64 stages
    Z_LOAD(0);
    Z_LOAD(1);
    for (int s = 0; s < NST; s++) {
        if (s + 2 < NST) {
            CP_WAIT1();
            __syncthreads();
            Z_LOAD(s + 2);
        } else {
            CP_WAIT0();
            __syncthreads();
        }

        const uint32_t buf = smb + (s % 3) * Z_STAGE;
        #pragma unroll
        for (int kk = 0; kk < 2; kk++) {
            const int kb = kk * 16;
            uint32_t Af[4][4], Bfh[4][2], Bfl[4][2];
            #pragma unroll
            for (int mi = 0; mi < 4; mi++) {
                uint32_t ad = buf + ((wm * 64 + mi * 16 + a_row) * ASTR + kb + a_col) * 2;
                LDSM4(Af[mi][0], Af[mi][1], Af[mi][2], Af[mi][3], ad);
            }
            #pragma unroll
            for (int jj = 0; jj < 2; jj++) {
                uint32_t ad = buf + Z_AMATB +
                              ((kb + bz_row) * Z_BSTR + wn * 32 + jj * 16 + bz_col) * 2;
                uint32_t t0, t1, t2, t3;
                LDSM4T(t0, t1, t2, t3, ad);
                Bfh[jj * 2][0] = t0; Bfh[jj * 2][1] = t1;
                Bfh[jj * 2 + 1][0] = t2; Bfh[jj * 2 + 1][1] = t3;
                LDSM4T(t0, t1, t2, t3, ad + Z_BMATB);
                Bfl[jj * 2][0] = t0; Bfl[jj * 2][1] = t1;
                Bfl[jj * 2 + 1][0] = t2; Bfl[jj * 2 + 1][1] = t3;
            }
            #pragma unroll
            for (int mi = 0; mi < 4; mi++)
                #pragma unroll
                for (int ni = 0; ni < 4; ni++) {
                    MMA_F16(acc[mi][ni], Af[mi], Bfh[ni][0], Bfh[ni][1]);
                    MMA_F16(acc[mi][ni], Af[mi], Bfl[ni][0], Bfl[ni][1]);
                }
        }
        __syncthreads();
    }
    #undef Z_LOAD

    float* Zo = Zp + (size_t)ks * ZPART;
    #pragma unroll
    for (int mi = 0; mi < 4; mi++)
        #pragma unroll
        for (int ni = 0; ni < 4; ni++) {
            const int row = bm + wm * 64 + mi * 16 + (lane >> 2);
            const int col = bn + wn * 32 + ni * 8 + (lane & 3) * 2;
            float* p = Zo + ((size_t)b * RB + row) * Dq + col;
            *(float2*)p = make_float2(acc[mi][ni][0], acc[mi][ni][1]);
            *(float2*)(p + (size_t)8 * Dq) = make_float2(acc[mi][ni][2], acc[mi][ni][3]);
        }
}

// =================================================================================
// ctx[b,h,uu,dh] = sum_e (Zp0+Zp1)[b, h*48+uu, e] * Wv[h*64+dh, e] -> Y
// =================================================================================
__global__ __launch_bounds__(256) void ctx_kernel(
    const float* __restrict__ Zp, const float* __restrict__ Wv,
    float* __restrict__ Y, int u)
{
    __shared__ float Zs[44 * 132];
    const int tid = threadIdx.x;
    const int bh = blockIdx.x;
    const int b = bh >> 4, h = bh & 15;
    const int dh = tid & 63, tg = tid >> 6;

    float acc[11];
    #pragma unroll
    for (int j = 0; j < 11; j++) acc[j] = 0.f;

    for (int e0 = 0; e0 < Dq; e0 += 128) {
        __syncthreads();
        for (int i = tid; i < 44 * 128; i += 256) {
            int uu = i >> 7, e = i & 127;
            float z = 0.f;
            if (uu < u) {
                size_t o = ((size_t)b * RB + h * RPAD + uu) * Dq + e0 + e;
                z = Zp[o] + Zp[o + ZPART];
            }
            Zs[uu * 132 + e] = z;
        }
        __syncthreads();

        const float* wv = Wv + (size_t)(h * 64 + dh) * Dq + e0;
        for (int e = 0; e < 128; e++) {
            float w = __ldg(&wv[e]);
            #pragma unroll
            for (int j = 0; j < 11; j++)
                acc[j] = fmaf(Zs[(tg + 4 * j) * 132 + e], w, acc[j]);
        }
    }

    #pragma unroll
    for (int j = 0; j < 11; j++) {
        int uu = tg + 4 * j;
        if (uu < u)
            Y[((size_t)(b * u + uu)) * Dq + h * 64 + dh] = acc[j];
    }
}

// =================================================================================
// Mean ctx row -> project through Wo^T + bo -> per-batch constant output row.
// =================================================================================
__global__ __launch_bounds__(128) void meanproj_kernel(
    const float* __restrict__ Y, const float* __restrict__ Wo,
    const float* __restrict__ bo, float* __restrict__ om, int u)
{
    __shared__ __align__(16) float ym[Dq];
    const int b = blockIdx.y;
    const int n0 = blockIdx.x * 128;

    for (int d = threadIdx.x; d < Dq; d += 128) {
        float sacc = 0.f;
        for (int j = 0; j < u; j++) sacc += Y[((size_t)(b * u + j)) * Dq + d];
        ym[d] = sacc * (1.f / (float)u);
    }
    __syncthreads();

    const int n = n0 + threadIdx.x;
    const float4* wrow = (const float4*)(Wo + (size_t)n * Dq);
    float accv = bo[n];
    #pragma unroll 4
    for (int d4 = 0; d4 < Dq / 4; d4++) {
        float4 w  = wrow[d4];
        float4 y4 = *(const float4*)&ym[d4 * 4];
        accv = fmaf(y4.x, w.x, accv);
        accv = fmaf(y4.y, w.y, accv);
        accv = fmaf(y4.z, w.z, accv);
        accv = fmaf(y4.w, w.w, accv);
    }
    om[b * Dq + n] = accv;
}

// =================================================================================
// Broadcast fill: out[b,t,:] = om[b,:] (idx rows overwritten after).
// =================================================================================
__global__ __launch_bounds__(256) void fill_kernel(
    const float4* __restrict__ om4, float4* __restrict__ out4)
{
    const int total4 = Bq * Tq * (Dq / 4);
    for (int i = blockIdx.x * blockDim.x + threadIdx.x; i < total4;
         i += gridDim.x * blockDim.x) {
        int c4 = i & 255;
        int bt = i >> 8;
        int b  = bt >> 12;
        out4[i] = __ldg(&om4[(b << 8) + c4]);
    }
}

// =================================================================================
extern "C" void kernel_launch(void* const* d_in, const int* in_sizes, int n_in,
                              void* d_out, int out_size)
{
    const float* x  = (const float*)d_in[0];
    const float* Wq = (const float*)d_in[1];
    const float* Wk = (const float*)d_in[2];
    const float* Wv = (const float*)d_in[3];
    const float* Wo = (const float*)d_in[4];
    const float* bo = (const float*)d_in[5];
    const int*  idx = (const int*)  d_in[6];
    const int u = in_sizes[6];                 // 41
    float* out = (float*)d_out;

    float *pS, *pZp, *pQs, *pY, *pom;
    __half *pxhi, *pxlo, *pQWh, *pPh;
    cudaGetSymbolAddress((void**)&pS,   g_S);
    cudaGetSymbolAddress((void**)&pZp,  g_Zp);
    cudaGetSymbolAddress((void**)&pQs,  g_Qs);
    cudaGetSymbolAddress((void**)&pY,   g_Y);
    cudaGetSymbolAddress((void**)&pom,  g_om);
    cudaGetSymbolAddress((void**)&pxhi, g_xhi);
    cudaGetSymbolAddress((void**)&pxlo, g_xlo);
    cudaGetSymbolAddress((void**)&pQWh, g_QWh);
    cudaGetSymbolAddress((void**)&pPh,  g_Ph);

    cudaFuncSetAttribute(gemm_s_tc, cudaFuncAttributeMaxDynamicSharedMemorySize, S_SMEM);
    cudaFuncSetAttribute(gemm_z_tc, cudaFuncAttributeMaxDynamicSharedMemorySize, Z_SMEM);

    const int Mu = Bq * u;                 // 328

    // 0) x -> fp16 hi/lo
    split_f16<<<2048, 256>>>((const float4*)x, (uint2*)pxhi, (uint2*)pxlo,
                             Bq * Tq * Dq / 4);

    // 1) Qs = x[idx rows] @ Wq^T  (fp32, tiny)
    sgemm_abt<<<dim3(Dq / 128, (Mu + 127) / 128), 256>>>(
        x, Wq, pQs, nullptr, Mu, Dq, Dq, Dq, Dq, Dq, idx, u, Tq, 1, 0);

    // 2) QW = 0.125 * (Qs per-head) @ Wk_head  -> fp16
    qw_kernel<<<dim3(Dq / 128, Bq * Hq), 256>>>(pQs, Wk, pQWh, u);

    // 3) S[b] = QW[b] @ x[b]^T  (tensor cores, 2-MMA fp16)
    gemm_s_tc<<<dim3(Tq / 128, RB / 128, Bq), 256, S_SMEM>>>(
        pQWh, pxhi, pxlo, pS);

    // 4) softmax rows -> P fp16
    softmax_kernel<<<Bq * RB, 256>>>(pS, pPh);

    // 5) Zp[ks][b] = P[b] @ x[b]  (tensor cores, split-K=2, 2-MMA fp16)
    gemm_z_tc<<<dim3(Dq / 128, RB / 128, Bq * 2), 256, Z_SMEM>>>(
        pPh, pxhi, pxlo, pZp);

    // 6) ctx = (Zp0+Zp1) @ Wv_head^T -> Y
    ctx_kernel<<<Bq * Hq, 256>>>(pZp, Wv, pY, u);

    // 7) per-batch mean ctx row -> @ Wo^T + bo
    meanproj_kernel<<<dim3(Dq / 128, Bq), 128>>>(pY, Wo, bo, pom, u);

    // 8) broadcast the constant row to all T positions
    fill_kernel<<<2048, 256>>>((const float4*)pom, (float4*)out);

    // 9) overwrite the u idx rows: out[b, idx[j], :] = Y_row @ Wo^T + bo
    sgemm_abt<<<dim3(Dq / 128, (Mu + 127) / 128), 256>>>(
        pY, Wo, out, bo, Mu, Dq, Dq, Dq, Dq, Dq, idx, u, Tq, 0, 1);
}

// round 7
// speedup vs baseline: 3.4199x; 1.1911x over previous
#include <cuda_runtime.h>
#include <cuda_fp16.h>
#include <cstdint>

// Problem constants (fixed by the dataset)
#define Bq  8
#define Tq  4096
#define Dq  1024
#define Hq  16
#define DHq 64
#define MAXU 64        // u = 41 at these shapes
#define RPAD 48        // per-head padded query rows (16*48 = 768 rows/batch)
#define RB   (Hq * RPAD)   // 768 rows per batch
#define ZPART ((size_t)Bq * RB * Dq)
#define PSCALE 1024.0f
#define PINV   (1.0f / 1024.0f)

// ---------------- scratch (static device memory; no allocations) ----------------
__device__ float  g_S  [(size_t)Bq * RB * Tq];        // scores fp32          96 MB
__device__ __half g_Ph [(size_t)Bq * RB * Tq];        // attn fp16 (x1024)    48 MB
__device__ __half g_xh [(size_t)Bq * Tq * Dq];        // x fp16               64 MB
__device__ __half g_QWh[(size_t)Bq * RB * Dq];        // QW fp16              12 MB
__device__ float  g_Zp [2 * ZPART];                   // split-K partials     48 MB
__device__ float  g_Qs [(size_t)Bq * MAXU * Dq];      // gathered Q proj
__device__ float  g_Y  [(size_t)Bq * MAXU * Dq];      // ctx rows
__device__ float  g_om [(size_t)Bq * Dq];             // per-batch output row

// ---------------- PTX helpers (sm_80-level, compile for plain sm_103) -----------
__device__ __forceinline__ uint32_t smem_u32(const void* p) {
    uint32_t a;
    asm("{ .reg .u64 t; cvta.to.shared.u64 t, %1; cvt.u32.u64 %0, t; }" : "=r"(a) : "l"(p));
    return a;
}
#define CP16(saddr, gptr) \
    asm volatile("cp.async.cg.shared.global [%0], [%1], 16;" :: "r"(saddr), "l"(gptr))
#define CP_COMMIT() asm volatile("cp.async.commit_group;")
#define CP_WAIT1()  asm volatile("cp.async.wait_group 1;")
#define CP_WAIT0()  asm volatile("cp.async.wait_group 0;")

#define LDSM4(r0,r1,r2,r3,addr) \
    asm volatile("ldmatrix.sync.aligned.m8n8.x4.shared.b16 {%0,%1,%2,%3}, [%4];" \
        : "=r"(r0),"=r"(r1),"=r"(r2),"=r"(r3) : "r"(addr))
#define LDSM4T(r0,r1,r2,r3,addr) \
    asm volatile("ldmatrix.sync.aligned.m8n8.x4.trans.shared.b16 {%0,%1,%2,%3}, [%4];" \
        : "=r"(r0),"=r"(r1),"=r"(r2),"=r"(r3) : "r"(addr))

#define MMA_F16(ac, A, b0, b1) \
    asm volatile("mma.sync.aligned.m16n8k16.row.col.f32.f16.f16.f32 " \
        "{%0,%1,%2,%3}, {%4,%5,%6,%7}, {%8,%9}, {%0,%1,%2,%3};" \
        : "+f"(ac[0]),"+f"(ac[1]),"+f"(ac[2]),"+f"(ac[3]) \
        : "r"(A[0]),"r"(A[1]),"r"(A[2]),"r"(A[3]), "r"(b0),"r"(b1))

// =================================================================================
// fp32 -> fp16 cast (for x)
// =================================================================================
__global__ __launch_bounds__(256) void cast_f16(
    const float4* __restrict__ src, uint2* __restrict__ hi, int n4)
{
    for (int i = blockIdx.x * 256 + threadIdx.x; i < n4; i += gridDim.x * 256) {
        float4 v = src[i];
        __half2 hA = {__float2half(v.x), __float2half(v.y)};
        __half2 hB = {__float2half(v.z), __float2half(v.w)};
        uint2 H;
        H.x = *(uint32_t*)&hA; H.y = *(uint32_t*)&hB;
        hi[i] = H;
    }
}

// =================================================================================
// Tiled fp32 SGEMM for the small gathered/scattered GEMMs
// =================================================================================
__global__ __launch_bounds__(256) void sgemm_abt(
    const float* __restrict__ A, const float* __restrict__ Bm, float* __restrict__ C,
    const float* __restrict__ bias, int M, int N, int K,
    int lda, int ldb, int ldc,
    const int* __restrict__ idx, int u, int Trows,
    int gatherA, int scatterC)
{
    __shared__ __align__(16) float As[16][132];
    __shared__ __align__(16) float Bs[16][132];

    const int tid = threadIdx.x;
    const int tx = tid & 15, ty = tid >> 4;
    const int bm = blockIdx.y * 128;
    const int bn = blockIdx.x * 128;

    const int lrow = tid >> 2;
    const int lk4  = (tid & 3) << 2;

    long long aoff[2]; bool aval[2];
    long long boff[2]; bool bval[2];
    #pragma unroll
    for (int i = 0; i < 2; i++) {
        int r = bm + lrow + i * 64;
        aval[i] = (r < M);
        int gr = 0;
        if (aval[i]) {
            gr = r;
            if (gatherA) { int bb = r / u; int jj = r - bb * u; gr = bb * Trows + idx[jj]; }
        }
        aoff[i] = (long long)gr * lda;
        int rn = bn + lrow + i * 64;
        bval[i] = (rn < N);
        boff[i] = (long long)(bval[i] ? rn : 0) * ldb;
    }

    float acc[8][8];
    #pragma unroll
    for (int i = 0; i < 8; i++)
        #pragma unroll
        for (int j = 0; j < 8; j++) acc[i][j] = 0.f;

    for (int k0 = 0; k0 < K; k0 += 16) {
        #pragma unroll
        for (int i = 0; i < 2; i++) {
            float4 v = make_float4(0.f, 0.f, 0.f, 0.f);
            if (aval[i]) v = *(const float4*)(A + aoff[i] + k0 + lk4);
            int rrw = lrow + i * 64;
            As[lk4 + 0][rrw] = v.x; As[lk4 + 1][rrw] = v.y;
            As[lk4 + 2][rrw] = v.z; As[lk4 + 3][rrw] = v.w;
            float4 w = make_float4(0.f, 0.f, 0.f, 0.f);
            if (bval[i]) w = *(const float4*)(Bm + boff[i] + k0 + lk4);
            Bs[lk4 + 0][rrw] = w.x; Bs[lk4 + 1][rrw] = w.y;
            Bs[lk4 + 2][rrw] = w.z; Bs[lk4 + 3][rrw] = w.w;
        }
        __syncthreads();

        #pragma unroll
        for (int kk = 0; kk < 16; kk++) {
            float a[8], b[8];
            *(float4*)&a[0] = *(const float4*)&As[kk][ty * 8];
            *(float4*)&a[4] = *(const float4*)&As[kk][ty * 8 + 4];
            *(float4*)&b[0] = *(const float4*)&Bs[kk][tx * 8];
            *(float4*)&b[4] = *(const float4*)&Bs[kk][tx * 8 + 4];
            #pragma unroll
            for (int i = 0; i < 8; i++)
                #pragma unroll
                for (int j = 0; j < 8; j++)
                    acc[i][j] = fmaf(a[i], b[j], acc[i][j]);
        }
        __syncthreads();
    }

    #pragma unroll
    for (int i = 0; i < 8; i++) {
        int m = bm + ty * 8 + i;
        if (m >= M) continue;
        long long crow = m;
        if (scatterC) { int bb = m / u; int jj = m - bb * u; crow = (long long)bb * Trows + idx[jj]; }
        float* cp = C + crow * ldc + bn + tx * 8;
        #pragma unroll
        for (int j = 0; j < 8; j++) {
            float v = acc[i][j];
            if (bias) v += bias[bn + tx * 8 + j];
            cp[j] = v;
        }
    }
}

// =================================================================================
// QW[b, h*48+uu, :] = 0.125 * Qs[b,uu, head] @ Wk[head, :]  -> fp16
// =================================================================================
__global__ __launch_bounds__(256) void qw_kernel(
    const float* __restrict__ Qs, const float* __restrict__ Wk,
    __half* __restrict__ QWh, int u)
{
    __shared__ float As[RPAD * 64];
    const int tid = threadIdx.x;
    const int bh = blockIdx.y;
    const int b = bh >> 4, h = bh & 15;
    const int n0 = blockIdx.x * 128;

    for (int i = tid; i < RPAD * 64; i += 256) {
        int uu = i >> 6, d = i & 63;
        As[i] = (uu < u) ? Qs[((size_t)(b * u + uu)) * Dq + h * 64 + d] : 0.f;
    }
    __syncthreads();

    const int n = n0 + (tid & 127);
    const int half_ = tid >> 7;
    float acc[24];
    #pragma unroll
    for (int j = 0; j < 24; j++) acc[j] = 0.f;

    for (int d = 0; d < 64; d++) {
        float w = __ldg(&Wk[(size_t)(h * 64 + d) * Dq + n]);
        #pragma unroll
        for (int j = 0; j < 24; j++)
            acc[j] = fmaf(As[(half_ * 24 + j) * 64 + d], w, acc[j]);
    }

    #pragma unroll
    for (int j = 0; j < 24; j++) {
        int uu = half_ * 24 + j;
        size_t o = ((size_t)b * RB + h * RPAD + uu) * Dq + n;
        QWh[o] = __float2half(acc[j] * 0.125f);
    }
}

// =================================================================================
// GEMM-S: S[b] = QW[b] @ x[b]^T   BM=128 BN=128 BK=32, 3-stage pipeline, 1 MMA.
// grid (Tq/128=32, RB/128=6, B=8)
// =================================================================================
#define ASTR 40                        // smem row stride in fp16 elems (80B)
#define S_MATB (128 * ASTR * 2)        // 10240 B per matrix
#define S_STAGE (2 * S_MATB)           // A, B = 20480
#define S_SMEM (3 * S_STAGE)           // 61440

__global__ __launch_bounds__(256) void gemm_s_tc(
    const __half* __restrict__ QWh, const __half* __restrict__ xh,
    float* __restrict__ S)
{
    extern __shared__ __align__(16) char smraw[];
    const uint32_t smb = smem_u32(smraw);

    const int tid = threadIdx.x;
    const int wid = tid >> 5, lane = tid & 31;
    const int wm = wid >> 2, wn = wid & 3;
    const int lr = lane & 7, quad = lane >> 3;

    const int b  = blockIdx.z;
    const int bm = blockIdx.y * 128;
    const int bn = blockIdx.x * 128;

    const __half* Ah = QWh + ((size_t)b * RB + bm) * Dq;
    const __half* Bh = xh  + ((size_t)b * Tq + bn) * Dq;

    const uint32_t a_row = lr + ((quad & 1) << 3);
    const uint32_t a_col = (quad >> 1) << 3;
    const uint32_t b_row = lr + ((quad >> 1) << 3);
    const uint32_t b_col = (quad & 1) << 3;

    float acc[4][4][4];
    #pragma unroll
    for (int i = 0; i < 4; i++)
        #pragma unroll
        for (int j = 0; j < 4; j++)
            #pragma unroll
            for (int k = 0; k < 4; k++) acc[i][j][k] = 0.f;

    const int ldrow = tid >> 2;
    const int ldc16 = (tid & 3) * 8;

    #define S_LOAD(st) do { \
        const int k0 = (st) * 32; \
        const uint32_t base = smb + ((st) % 3) * S_STAGE; \
        _Pragma("unroll") \
        for (int i = 0; i < 2; i++) { \
            const int row = ldrow + i * 64; \
            const size_t g = (size_t)row * Dq + k0 + ldc16; \
            const uint32_t so = (row * ASTR + ldc16) * 2; \
            CP16(base + so,          Ah + g); \
            CP16(base + S_MATB + so, Bh + g); \
        } \
        CP_COMMIT(); \
    } while (0)

    const int NST = Dq / 32;                    // 32 stages
    S_LOAD(0);
    S_LOAD(1);
    for (int s = 0; s < NST; s++) {
        if (s + 2 < NST) {
            CP_WAIT1();
            __syncthreads();
            S_LOAD(s + 2);
        } else {
            CP_WAIT0();
            __syncthreads();
        }

        const uint32_t buf = smb + (s % 3) * S_STAGE;
        #pragma unroll
        for (int kk = 0; kk < 2; kk++) {
            const int kb = kk * 16;
            uint32_t Af[4][4], Bf[4][2];
            #pragma unroll
            for (int mi = 0; mi < 4; mi++) {
                uint32_t ad = buf + ((wm * 64 + mi * 16 + a_row) * ASTR + kb + a_col) * 2;
                LDSM4(Af[mi][0], Af[mi][1], Af[mi][2], Af[mi][3], ad);
            }
            #pragma unroll
            for (int jj = 0; jj < 2; jj++) {
                uint32_t ad = buf + S_MATB +
                              ((wn * 32 + jj * 16 + b_row) * ASTR + kb + b_col) * 2;
                uint32_t t0, t1, t2, t3;
                LDSM4(t0, t1, t2, t3, ad);
                Bf[jj * 2][0] = t0; Bf[jj * 2][1] = t1;
                Bf[jj * 2 + 1][0] = t2; Bf[jj * 2 + 1][1] = t3;
            }
            #pragma unroll
            for (int mi = 0; mi < 4; mi++)
                #pragma unroll
                for (int ni = 0; ni < 4; ni++)
                    MMA_F16(acc[mi][ni], Af[mi], Bf[ni][0], Bf[ni][1]);
        }
        __syncthreads();
    }
    #undef S_LOAD

    #pragma unroll
    for (int mi = 0; mi < 4; mi++)
        #pragma unroll
        for (int ni = 0; ni < 4; ni++) {
            const int row = bm + wm * 64 + mi * 16 + (lane >> 2);
            const int col = bn + wn * 32 + ni * 8 + (lane & 3) * 2;
            float* p = S + ((size_t)b * RB + row) * Tq + col;
            *(float2*)p = make_float2(acc[mi][ni][0], acc[mi][ni][1]);
            *(float2*)(p + (size_t)8 * Tq) = make_float2(acc[mi][ni][2], acc[mi][ni][3]);
        }
}

// =================================================================================
// Softmax over T per row; writes P (x PSCALE) as fp16. One block per row.
// =================================================================================
__global__ __launch_bounds__(256) void softmax_kernel(
    const float* __restrict__ S, __half* __restrict__ Ph)
{
    __shared__ float red[8], red2[8];
    const size_t row = blockIdx.x;
    const float* src = S + row * Tq;
    const int tid = threadIdx.x;
    const int wid = tid >> 5, lane = tid & 31;

    float v[16];
    #pragma unroll
    for (int i = 0; i < 16; i++) v[i] = src[tid + (i << 8)];

    float m = v[0];
    #pragma unroll
    for (int i = 1; i < 16; i++) m = fmaxf(m, v[i]);
    #pragma unroll
    for (int o = 16; o > 0; o >>= 1) m = fmaxf(m, __shfl_xor_sync(0xffffffffu, m, o));
    if (lane == 0) red[wid] = m;
    __syncthreads();
    float M = red[0];
    #pragma unroll
    for (int w = 1; w < 8; w++) M = fmaxf(M, red[w]);

    float sum = 0.f;
    #pragma unroll
    for (int i = 0; i < 16; i++) { v[i] = __expf(v[i] - M); sum += v[i]; }
    #pragma unroll
    for (int o = 16; o > 0; o >>= 1) sum += __shfl_xor_sync(0xffffffffu, sum, o);
    if (lane == 0) red2[wid] = sum;
    __syncthreads();
    float L = 0.f;
    #pragma unroll
    for (int w = 0; w < 8; w++) L += red2[w];
    const float inv = PSCALE / L;

    #pragma unroll
    for (int i = 0; i < 16; i++)
        Ph[row * Tq + tid + (i << 8)] = __float2half(v[i] * inv);
}

// =================================================================================
// GEMM-Z: Zp[ks][b] = P[b][:, ksplit] @ x[b][ksplit, :]
//   BM=128 BN=128 BK=32, split-K=2, 3-stage pipeline, 1 MMA.
// grid (Dq/128=8, RB/128=6, B*2=16)
// =================================================================================
#define Z_AMATB (128 * ASTR * 2)       // 10240
#define Z_BSTR 136
#define Z_BMATB (32 * Z_BSTR * 2)      // 8704
#define Z_STAGE (Z_AMATB + Z_BMATB)    // 18944
#define Z_SMEM (3 * Z_STAGE)           // 56832
#define KSPL (Tq / 2)                  // 2048

__global__ __launch_bounds__(256) void gemm_z_tc(
    const __half* __restrict__ Ph, const __half* __restrict__ xh,
    float* __restrict__ Zp)
{
    extern __shared__ __align__(16) char smraw[];
    const uint32_t smb = smem_u32(smraw);

    const int tid = threadIdx.x;
    const int wid = tid >> 5, lane = tid & 31;
    const int wm = wid >> 2, wn = wid & 3;
    const int lr = lane & 7, quad = lane >> 3;

    const int b  = blockIdx.z >> 1;
    const int ks = blockIdx.z & 1;
    const int bm = blockIdx.y * 128;
    const int bn = blockIdx.x * 128;

    const __half* Ah = Ph + ((size_t)b * RB + bm) * Tq + (size_t)ks * KSPL;
    const __half* Bh = xh + ((size_t)b * Tq + (size_t)ks * KSPL) * Dq;

    const uint32_t a_row = lr + ((quad & 1) << 3);
    const uint32_t a_col = (quad >> 1) << 3;
    const uint32_t bz_row = lr + ((quad & 1) << 3);   // k dir
    const uint32_t bz_col = (quad >> 1) << 3;         // n dir

    float acc[4][4][4];
    #pragma unroll
    for (int i = 0; i < 4; i++)
        #pragma unroll
        for (int j = 0; j < 4; j++)
            #pragma unroll
            for (int k = 0; k < 4; k++) acc[i][j][k] = 0.f;

    const int arow = tid >> 2;                 // 0..63
    const int ac16 = (tid & 3) * 8;

    #define Z_LOAD(st) do { \
        const int k0 = (st) * 32; \
        const uint32_t base = smb + ((st) % 3) * Z_STAGE; \
        _Pragma("unroll") \
        for (int i = 0; i < 2; i++) { \
            const int row = arow + i * 64; \
            const size_t g = (size_t)row * Tq + k0 + ac16; \
            const uint32_t so = (row * ASTR + ac16) * 2; \
            CP16(base + so, Ah + g); \
        } \
        _Pragma("unroll") \
        for (int i = 0; i < 2; i++) { \
            const int idx = tid + i * 256; \
            const int brow = idx >> 4, bc = (idx & 15) * 8; \
            const size_t g = (size_t)(k0 + brow) * Dq + bn + bc; \
            const uint32_t so = (brow * Z_BSTR + bc) * 2; \
            CP16(base + Z_AMATB + so, Bh + g); \
        } \
        CP_COMMIT(); \
    } while (0)

    const int NST = KSPL / 32;                 // 64 stages
    Z_LOAD(0);
    Z_LOAD(1);
    for (int s = 0; s < NST; s++) {
        if (s + 2 < NST) {
            CP_WAIT1();
            __syncthreads();
            Z_LOAD(s + 2);
        } else {
            CP_WAIT0();
            __syncthreads();
        }

        const uint32_t buf = smb + (s % 3) * Z_STAGE;
        #pragma unroll
        for (int kk = 0; kk < 2; kk++) {
            const int kb = kk * 16;
            uint32_t Af[4][4], Bf[4][2];
            #pragma unroll
            for (int mi = 0; mi < 4; mi++) {
                uint32_t ad = buf + ((wm * 64 + mi * 16 + a_row) * ASTR + kb + a_col) * 2;
                LDSM4(Af[mi][0], Af[mi][1], Af[mi][2], Af[mi][3], ad);
            }
            #pragma unroll
            for (int jj = 0; jj < 2; jj++) {
                uint32_t ad = buf + Z_AMATB +
                              ((kb + bz_row) * Z_BSTR + wn * 32 + jj * 16 + bz_col) * 2;
                uint32_t t0, t1, t2, t3;
                LDSM4T(t0, t1, t2, t3, ad);
                Bf[jj * 2][0] = t0; Bf[jj * 2][1] = t1;
                Bf[jj * 2 + 1][0] = t2; Bf[jj * 2 + 1][1] = t3;
            }
            #pragma unroll
            for (int mi = 0; mi < 4; mi++)
                #pragma unroll
                for (int ni = 0; ni < 4; ni++)
                    MMA_F16(acc[mi][ni], Af[mi], Bf[ni][0], Bf[ni][1]);
        }
        __syncthreads();
    }
    #undef Z_LOAD

    float* Zo = Zp + (size_t)ks * ZPART;
    #pragma unroll
    for (int mi = 0; mi < 4; mi++)
        #pragma unroll
        for (int ni = 0; ni < 4; ni++) {
            const int row = bm + wm * 64 + mi * 16 + (lane >> 2);
            const int col = bn + wn * 32 + ni * 8 + (lane & 3) * 2;
            float* p = Zo + ((size_t)b * RB + row) * Dq + col;
            *(float2*)p = make_float2(acc[mi][ni][0], acc[mi][ni][1]);
            *(float2*)(p + (size_t)8 * Dq) = make_float2(acc[mi][ni][2], acc[mi][ni][3]);
        }
}

// =================================================================================
// ctx[b,h,uu,dh] = PINV * sum_e (Zp0+Zp1)[b, h*48+uu, e] * Wv[h*64+dh, e] -> Y
// =================================================================================
__global__ __launch_bounds__(256) void ctx_kernel(
    const float* __restrict__ Zp, const float* __restrict__ Wv,
    float* __restrict__ Y, int u)
{
    __shared__ float Zs[44 * 132];
    const int tid = threadIdx.x;
    const int bh = blockIdx.x;
    const int b = bh >> 4, h = bh & 15;
    const int dh = tid & 63, tg = tid >> 6;

    float acc[11];
    #pragma unroll
    for (int j = 0; j < 11; j++) acc[j] = 0.f;

    for (int e0 = 0; e0 < Dq; e0 += 128) {
        __syncthreads();
        for (int i = tid; i < 44 * 128; i += 256) {
            int uu = i >> 7, e = i & 127;
            float z = 0.f;
            if (uu < u) {
                size_t o = ((size_t)b * RB + h * RPAD + uu) * Dq + e0 + e;
                z = Zp[o] + Zp[o + ZPART];
            }
            Zs[uu * 132 + e] = z;
        }
        __syncthreads();

        const float* wv = Wv + (size_t)(h * 64 + dh) * Dq + e0;
        for (int e = 0; e < 128; e++) {
            float w = __ldg(&wv[e]);
            #pragma unroll
            for (int j = 0; j < 11; j++)
                acc[j] = fmaf(Zs[(tg + 4 * j) * 132 + e], w, acc[j]);
        }
    }

    #pragma unroll
    for (int j = 0; j < 11; j++) {
        int uu = tg + 4 * j;
        if (uu < u)
            Y[((size_t)(b * u + uu)) * Dq + h * 64 + dh] = acc[j] * PINV;
    }
}

// =================================================================================
// Mean ctx row -> project through Wo^T + bo -> per-batch constant output row.
// =================================================================================
__global__ __launch_bounds__(128) void meanproj_kernel(
    const float* __restrict__ Y, const float* __restrict__ Wo,
    const float* __restrict__ bo, float* __restrict__ om, int u)
{
    __shared__ __align__(16) float ym[Dq];
    const int b = blockIdx.y;
    const int n0 = blockIdx.x * 128;

    for (int d = threadIdx.x; d < Dq; d += 128) {
        float sacc = 0.f;
        for (int j = 0; j < u; j++) sacc += Y[((size_t)(b * u + j)) * Dq + d];
        ym[d] = sacc * (1.f / (float)u);
    }
    __syncthreads();

    const int n = n0 + threadIdx.x;
    const float4* wrow = (const float4*)(Wo + (size_t)n * Dq);
    float accv = bo[n];
    #pragma unroll 4
    for (int d4 = 0; d4 < Dq / 4; d4++) {
        float4 w  = wrow[d4];
        float4 y4 = *(const float4*)&ym[d4 * 4];
        accv = fmaf(y4.x, w.x, accv);
        accv = fmaf(y4.y, w.y, accv);
        accv = fmaf(y4.z, w.z, accv);
        accv = fmaf(y4.w, w.w, accv);
    }
    om[b * Dq + n] = accv;
}

// =================================================================================
// Broadcast fill: out[b,t,:] = om[b,:] (idx rows overwritten after).
// =================================================================================
__global__ __launch_bounds__(256) void fill_kernel(
    const float4* __restrict__ om4, float4* __restrict__ out4)
{
    const int total4 = Bq * Tq * (Dq / 4);
    for (int i = blockIdx.x * blockDim.x + threadIdx.x; i < total4;
         i += gridDim.x * blockDim.x) {
        int c4 = i & 255;
        int bt = i >> 8;
        int b  = bt >> 12;
        out4[i] = __ldg(&om4[(b << 8) + c4]);
    }
}

// =================================================================================
extern "C" void kernel_launch(void* const* d_in, const int* in_sizes, int n_in,
                              void* d_out, int out_size)
{
    const float* x  = (const float*)d_in[0];
    const float* Wq = (const float*)d_in[1];
    const float* Wk = (const float*)d_in[2];
    const float* Wv = (const float*)d_in[3];
    const float* Wo = (const float*)d_in[4];
    const float* bo = (const float*)d_in[5];
    const int*  idx = (const int*)  d_in[6];
    const int u = in_sizes[6];                 // 41
    float* out = (float*)d_out;

    float *pS, *pZp, *pQs, *pY, *pom;
    __half *pxh, *pQWh, *pPh;
    cudaGetSymbolAddress((void**)&pS,   g_S);
    cudaGetSymbolAddress((void**)&pZp,  g_Zp);
    cudaGetSymbolAddress((void**)&pQs,  g_Qs);
    cudaGetSymbolAddress((void**)&pY,   g_Y);
    cudaGetSymbolAddress((void**)&pom,  g_om);
    cudaGetSymbolAddress((void**)&pxh,  g_xh);
    cudaGetSymbolAddress((void**)&pQWh, g_QWh);
    cudaGetSymbolAddress((void**)&pPh,  g_Ph);

    cudaFuncSetAttribute(gemm_s_tc, cudaFuncAttributeMaxDynamicSharedMemorySize, S_SMEM);
    cudaFuncSetAttribute(gemm_z_tc, cudaFuncAttributeMaxDynamicSharedMemorySize, Z_SMEM);

    const int Mu = Bq * u;                 // 328

    // 0) x -> fp16
    cast_f16<<<2048, 256>>>((const float4*)x, (uint2*)pxh, Bq * Tq * Dq / 4);

    // 1) Qs = x[idx rows] @ Wq^T  (fp32, tiny)
    sgemm_abt<<<dim3(Dq / 128, (Mu + 127) / 128), 256>>>(
        x, Wq, pQs, nullptr, Mu, Dq, Dq, Dq, Dq, Dq, idx, u, Tq, 1, 0);

    // 2) QW = 0.125 * (Qs per-head) @ Wk_head  -> fp16
    qw_kernel<<<dim3(Dq / 128, Bq * Hq), 256>>>(pQs, Wk, pQWh, u);

    // 3) S[b] = QW[b] @ x[b]^T  (tensor cores, single fp16 MMA)
    gemm_s_tc<<<dim3(Tq / 128, RB / 128, Bq), 256, S_SMEM>>>(pQWh, pxh, pS);

    // 4) softmax rows -> P fp16 (x1024)
    softmax_kernel<<<Bq * RB, 256>>>(pS, pPh);

    // 5) Zp[ks][b] = P[b] @ x[b]  (tensor cores, split-K=2, single fp16 MMA)
    gemm_z_tc<<<dim3(Dq / 128, RB / 128, Bq * 2), 256, Z_SMEM>>>(pPh, pxh, pZp);

    // 6) ctx = PINV * (Zp0+Zp1) @ Wv_head^T -> Y
    ctx_kernel<<<Bq * Hq, 256>>>(pZp, Wv, pY, u);

    // 7) per-batch mean ctx row -> @ Wo^T + bo
    meanproj_kernel<<<dim3(Dq / 128, Bq), 128>>>(pY, Wo, bo, pom, u);

    // 8) broadcast the constant row to all T positions
    fill_kernel<<<2048, 256>>>((const float4*)pom, (float4*)out);

    // 9) overwrite the u idx rows: out[b, idx[j], :] = Y_row @ Wo^T + bo
    sgemm_abt<<<dim3(Dq / 128, (Mu + 127) / 128), 256>>>(
        pY, Wo, out, bo, Mu, Dq, Dq, Dq, Dq, Dq, idx, u, Tq, 0, 1);
}